// round 2
// baseline (speedup 1.0000x reference)
#include <cuda_runtime.h>

// Problem constants
#define BATCH  131072
#define NND    512
#define DIN    4
#define NLAYER 3

// -------- scratch (device globals; no allocation allowed) --------
__device__ float g_H0[(size_t)BATCH * NND];
__device__ float g_H1[(size_t)BATCH * NND];
__device__ float g_F [(size_t)BATCH * NND];
__device__ float g_P [(size_t)BATCH * NND];

// -------- f32x2 packed-FMA helpers (FFMA2: 2x fp32 FMA throughput on sm_103a) --------
__device__ __forceinline__ unsigned long long pack2(float a, float b) {
    unsigned long long r;
    asm("mov.b64 %0, {%1, %2};" : "=l"(r) : "f"(a), "f"(b));
    return r;
}
__device__ __forceinline__ unsigned long long fma2(unsigned long long a, unsigned long long b, unsigned long long c) {
    unsigned long long d;
    asm("fma.rn.f32x2 %0, %1, %2, %3;" : "=l"(d) : "l"(a), "l"(b), "l"(c));
    return d;
}
__device__ __forceinline__ float2 unpack2(unsigned long long v) {
    float2 f;
    asm("mov.b64 {%0, %1}, %2;" : "=f"(f.x), "=f"(f.y) : "l"(v));
    return f;
}

// -------- activations --------
__device__ __forceinline__ float fsigmoid(float x) {
    return __fdividef(1.0f, 1.0f + __expf(-x));
}
__device__ __forceinline__ float ftanh_(float x) {
    // 1 - 2/(e^{2x}+1); handles +-inf limits correctly via __expf saturation
    return 1.0f - __fdividef(2.0f, __expf(2.0f * x) + 1.0f);
}
__device__ __forceinline__ float fsilu(float x) {
    return x * fsigmoid(x);
}

// ================= kernel 1: H = silu(X @ W_in + b_in) =================
__global__ __launch_bounds__(256) void k_init(
    const float* __restrict__ X, const float* __restrict__ W_in, const float* __restrict__ b_in)
{
    int idx = blockIdx.x * 256 + threadIdx.x;      // over BATCH*NND
    int m = idx >> 9;
    int j = idx & (NND - 1);
    float4 xv = reinterpret_cast<const float4*>(X)[m];
    float a = b_in[j]
            + xv.x * W_in[j]
            + xv.y * W_in[NND + j]
            + xv.z * W_in[2 * NND + j]
            + xv.w * W_in[3 * NND + j];
    g_H0[idx] = fsilu(a);
}

// ================= kernel 2: 3-way gated GEMM =================
// For a tile of rows: pre_f = X@Wf + H@Uf + bf (and same for u, o1).
// Writes F = sigmoid(pre_f), P = sigmoid(pre_u) * tanh(pre_o1).
// BM=128, BN=64, BK=16, 256 threads, per-thread 8x4 outputs x 3 matrices.
__global__ __launch_bounds__(256) void k_gate(
    int layer, const float* __restrict__ X,
    const float* __restrict__ Wf_, const float* __restrict__ Uf_, const float* __restrict__ bf_,
    const float* __restrict__ Wu_, const float* __restrict__ Uu_, const float* __restrict__ bu_,
    const float* __restrict__ Wo_, const float* __restrict__ Uo_, const float* __restrict__ bo_)
{
    const float* __restrict__ H = (layer & 1) ? g_H1 : g_H0;

    __shared__ __align__(16) float As[16][132];        // [k][m], padded stride
    __shared__ __align__(16) float Bs[3][16][64];      // [mat][k][j]
    __shared__ __align__(16) float4 Xs[128];

    const int tid = threadIdx.x;
    const int m0 = blockIdx.y * 128;
    const int j0 = blockIdx.x * 64;
    const int tx = tid & 15;           // col group: cols j0 + tx*4 .. +3
    const int ty = tid >> 4;           // row group: rows m0 + ty*8 .. +7
    const int ar = tid >> 2;           // A loader row (0..63)
    const int ac = (tid & 3) * 4;      // A loader col (0,4,8,12)
    const int br = tid >> 4;           // B loader row (0..15)
    const int bc = (tid & 15) * 4;     // B loader col

    if (tid < 128) Xs[tid] = reinterpret_cast<const float4*>(X)[m0 + tid];

    const float* Ap0 = H + (size_t)(m0 + ar) * NND + ac;
    const float* Ap1 = H + (size_t)(m0 + ar + 64) * NND + ac;
    const float* Bfp = Uf_ + (size_t)br * NND + j0 + bc;
    const float* Bup = Uu_ + (size_t)br * NND + j0 + bc;
    const float* Bop = Uo_ + (size_t)br * NND + j0 + bc;

    unsigned long long aF[8][2], aU[8][2], aO[8][2];
#pragma unroll
    for (int i = 0; i < 8; ++i) {
        aF[i][0] = 0ull; aF[i][1] = 0ull;
        aU[i][0] = 0ull; aU[i][1] = 0ull;
        aO[i][0] = 0ull; aO[i][1] = 0ull;
    }

    float4 pa0 = *reinterpret_cast<const float4*>(Ap0);
    float4 pa1 = *reinterpret_cast<const float4*>(Ap1);
    float4 pf  = *reinterpret_cast<const float4*>(Bfp);
    float4 pu  = *reinterpret_cast<const float4*>(Bup);
    float4 po  = *reinterpret_cast<const float4*>(Bop);

#pragma unroll 1
    for (int kt = 0; kt < NND / 16; ++kt) {
        __syncthreads();
        As[ac + 0][ar]      = pa0.x; As[ac + 1][ar]      = pa0.y;
        As[ac + 2][ar]      = pa0.z; As[ac + 3][ar]      = pa0.w;
        As[ac + 0][ar + 64] = pa1.x; As[ac + 1][ar + 64] = pa1.y;
        As[ac + 2][ar + 64] = pa1.z; As[ac + 3][ar + 64] = pa1.w;
        *reinterpret_cast<float4*>(&Bs[0][br][bc]) = pf;
        *reinterpret_cast<float4*>(&Bs[1][br][bc]) = pu;
        *reinterpret_cast<float4*>(&Bs[2][br][bc]) = po;
        __syncthreads();

        if (kt < NND / 16 - 1) {
            Ap0 += 16; Ap1 += 16;
            Bfp += 16 * NND; Bup += 16 * NND; Bop += 16 * NND;
            pa0 = *reinterpret_cast<const float4*>(Ap0);
            pa1 = *reinterpret_cast<const float4*>(Ap1);
            pf  = *reinterpret_cast<const float4*>(Bfp);
            pu  = *reinterpret_cast<const float4*>(Bup);
            po  = *reinterpret_cast<const float4*>(Bop);
        }

#pragma unroll
        for (int k = 0; k < 16; ++k) {
            float4 a0 = *reinterpret_cast<const float4*>(&As[k][ty * 8]);
            float4 a1 = *reinterpret_cast<const float4*>(&As[k][ty * 8 + 4]);
            unsigned long long aa[8];
            aa[0] = pack2(a0.x, a0.x); aa[1] = pack2(a0.y, a0.y);
            aa[2] = pack2(a0.z, a0.z); aa[3] = pack2(a0.w, a0.w);
            aa[4] = pack2(a1.x, a1.x); aa[5] = pack2(a1.y, a1.y);
            aa[6] = pack2(a1.z, a1.z); aa[7] = pack2(a1.w, a1.w);
            ulonglong2 bf2 = *reinterpret_cast<const ulonglong2*>(&Bs[0][k][tx * 4]);
            ulonglong2 bu2 = *reinterpret_cast<const ulonglong2*>(&Bs[1][k][tx * 4]);
            ulonglong2 bo2 = *reinterpret_cast<const ulonglong2*>(&Bs[2][k][tx * 4]);
#pragma unroll
            for (int i = 0; i < 8; ++i) {
                aF[i][0] = fma2(aa[i], bf2.x, aF[i][0]);
                aF[i][1] = fma2(aa[i], bf2.y, aF[i][1]);
                aU[i][0] = fma2(aa[i], bu2.x, aU[i][0]);
                aU[i][1] = fma2(aa[i], bu2.y, aU[i][1]);
                aO[i][0] = fma2(aa[i], bo2.x, aO[i][0]);
                aO[i][1] = fma2(aa[i], bo2.y, aO[i][1]);
            }
        }
    }

    // epilogue: add X@W + bias, activate, write F and P
    const int jb = j0 + tx * 4;
#pragma unroll
    for (int i = 0; i < 8; ++i) {
        const int m = m0 + ty * 8 + i;
        float4 xv = Xs[ty * 8 + i];
        float2 f01 = unpack2(aF[i][0]), f23 = unpack2(aF[i][1]);
        float2 u01 = unpack2(aU[i][0]), u23 = unpack2(aU[i][1]);
        float2 o01 = unpack2(aO[i][0]), o23 = unpack2(aO[i][1]);
        float fr[4] = {f01.x, f01.y, f23.x, f23.y};
        float ur[4] = {u01.x, u01.y, u23.x, u23.y};
        float orr[4] = {o01.x, o01.y, o23.x, o23.y};
        float outF[4], outP[4];
#pragma unroll
        for (int c = 0; c < 4; ++c) {
            const int j = jb + c;
            float fpre = fr[c] + bf_[j] + xv.x * Wf_[j] + xv.y * Wf_[NND + j]
                       + xv.z * Wf_[2 * NND + j] + xv.w * Wf_[3 * NND + j];
            float upre = ur[c] + bu_[j] + xv.x * Wu_[j] + xv.y * Wu_[NND + j]
                       + xv.z * Wu_[2 * NND + j] + xv.w * Wu_[3 * NND + j];
            float opre = orr[c] + bo_[j] + xv.x * Wo_[j] + xv.y * Wo_[NND + j]
                       + xv.z * Wo_[2 * NND + j] + xv.w * Wo_[3 * NND + j];
            outF[c] = fsigmoid(fpre);
            outP[c] = fsigmoid(upre) * ftanh_(opre);
        }
        *reinterpret_cast<float4*>(&g_F[(size_t)m * NND + jb]) =
            make_float4(outF[0], outF[1], outF[2], outF[3]);
        *reinterpret_cast<float4*>(&g_P[(size_t)m * NND + jb]) =
            make_float4(outP[0], outP[1], outP[2], outP[3]);
    }
}

// ================= kernel 3: H_new = F*H + silu(P @ Wo2 + bo2) =================
// BM=128, BN=128, BK=16, 256 threads, per-thread 8x8 outputs.
__global__ __launch_bounds__(256) void k_gemm2(
    int layer, const float* __restrict__ W, const float* __restrict__ b2)
{
    const float* __restrict__ Hin  = (layer & 1) ? g_H1 : g_H0;
    float* __restrict__       Hout = (layer & 1) ? g_H0 : g_H1;

    __shared__ __align__(16) float As[16][132];
    __shared__ __align__(16) float Bs[16][128];

    const int tid = threadIdx.x;
    const int m0 = blockIdx.y * 128;
    const int j0 = blockIdx.x * 128;
    const int tx = tid & 15;           // cols j0 + tx*8 .. +7
    const int ty = tid >> 4;           // rows m0 + ty*8 .. +7
    const int ar = tid >> 2;
    const int ac = (tid & 3) * 4;
    const int br = tid >> 5;           // 0..7
    const int bc = (tid & 31) * 4;     // 0..124

    const float* Ap0 = g_P + (size_t)(m0 + ar) * NND + ac;
    const float* Ap1 = g_P + (size_t)(m0 + ar + 64) * NND + ac;
    const float* Bp0 = W + (size_t)br * NND + j0 + bc;
    const float* Bp1 = W + (size_t)(br + 8) * NND + j0 + bc;

    unsigned long long acc[8][4];
#pragma unroll
    for (int i = 0; i < 8; ++i)
#pragma unroll
        for (int c = 0; c < 4; ++c) acc[i][c] = 0ull;

    float4 pa0 = *reinterpret_cast<const float4*>(Ap0);
    float4 pa1 = *reinterpret_cast<const float4*>(Ap1);
    float4 pb0 = *reinterpret_cast<const float4*>(Bp0);
    float4 pb1 = *reinterpret_cast<const float4*>(Bp1);

#pragma unroll 1
    for (int kt = 0; kt < NND / 16; ++kt) {
        __syncthreads();
        As[ac + 0][ar]      = pa0.x; As[ac + 1][ar]      = pa0.y;
        As[ac + 2][ar]      = pa0.z; As[ac + 3][ar]      = pa0.w;
        As[ac + 0][ar + 64] = pa1.x; As[ac + 1][ar + 64] = pa1.y;
        As[ac + 2][ar + 64] = pa1.z; As[ac + 3][ar + 64] = pa1.w;
        *reinterpret_cast<float4*>(&Bs[br][bc])     = pb0;
        *reinterpret_cast<float4*>(&Bs[br + 8][bc]) = pb1;
        __syncthreads();

        if (kt < NND / 16 - 1) {
            Ap0 += 16; Ap1 += 16;
            Bp0 += 16 * NND; Bp1 += 16 * NND;
            pa0 = *reinterpret_cast<const float4*>(Ap0);
            pa1 = *reinterpret_cast<const float4*>(Ap1);
            pb0 = *reinterpret_cast<const float4*>(Bp0);
            pb1 = *reinterpret_cast<const float4*>(Bp1);
        }

#pragma unroll
        for (int k = 0; k < 16; ++k) {
            float4 a0 = *reinterpret_cast<const float4*>(&As[k][ty * 8]);
            float4 a1 = *reinterpret_cast<const float4*>(&As[k][ty * 8 + 4]);
            unsigned long long aa[8];
            aa[0] = pack2(a0.x, a0.x); aa[1] = pack2(a0.y, a0.y);
            aa[2] = pack2(a0.z, a0.z); aa[3] = pack2(a0.w, a0.w);
            aa[4] = pack2(a1.x, a1.x); aa[5] = pack2(a1.y, a1.y);
            aa[6] = pack2(a1.z, a1.z); aa[7] = pack2(a1.w, a1.w);
            ulonglong2 b01 = *reinterpret_cast<const ulonglong2*>(&Bs[k][tx * 8]);
            ulonglong2 b23 = *reinterpret_cast<const ulonglong2*>(&Bs[k][tx * 8 + 4]);
            unsigned long long bb[4] = {b01.x, b01.y, b23.x, b23.y};
#pragma unroll
            for (int i = 0; i < 8; ++i) {
#pragma unroll
                for (int c = 0; c < 4; ++c)
                    acc[i][c] = fma2(aa[i], bb[c], acc[i][c]);
            }
        }
    }

    // epilogue: H_new = F*H + silu(acc + bias)
    const int jb = j0 + tx * 8;
    float4 bias0 = *reinterpret_cast<const float4*>(&b2[jb]);
    float4 bias1 = *reinterpret_cast<const float4*>(&b2[jb + 4]);
    float bias[8] = {bias0.x, bias0.y, bias0.z, bias0.w, bias1.x, bias1.y, bias1.z, bias1.w};
#pragma unroll
    for (int i = 0; i < 8; ++i) {
        const int m = m0 + ty * 8 + i;
        const size_t base = (size_t)m * NND + jb;
        float2 v0 = unpack2(acc[i][0]), v1 = unpack2(acc[i][1]);
        float2 v2 = unpack2(acc[i][2]), v3 = unpack2(acc[i][3]);
        float o2[8] = {v0.x, v0.y, v1.x, v1.y, v2.x, v2.y, v3.x, v3.y};
        float4 fa = *reinterpret_cast<const float4*>(&g_F[base]);
        float4 fb = *reinterpret_cast<const float4*>(&g_F[base + 4]);
        float4 ha = *reinterpret_cast<const float4*>(&Hin[base]);
        float4 hb = *reinterpret_cast<const float4*>(&Hin[base + 4]);
        float fv[8] = {fa.x, fa.y, fa.z, fa.w, fb.x, fb.y, fb.z, fb.w};
        float hv[8] = {ha.x, ha.y, ha.z, ha.w, hb.x, hb.y, hb.z, hb.w};
        float hn[8];
#pragma unroll
        for (int c = 0; c < 8; ++c)
            hn[c] = fv[c] * hv[c] + fsilu(o2[c] + bias[c]);
        *reinterpret_cast<float4*>(&Hout[base])     = make_float4(hn[0], hn[1], hn[2], hn[3]);
        *reinterpret_cast<float4*>(&Hout[base + 4]) = make_float4(hn[4], hn[5], hn[6], hn[7]);
    }
}

// ================= kernel 4: out = silu(H @ W_out + b_out) =================
__global__ __launch_bounds__(256) void k_out(
    const float* __restrict__ W_out, const float* __restrict__ b_out, float* __restrict__ out)
{
    // after 3 layers the live H buffer is g_H1 (H0 -> H1 -> H0 -> H1)
    const float* __restrict__ H = g_H1;
    const int warp = threadIdx.x >> 5;
    const int lane = threadIdx.x & 31;
    const int row = blockIdx.x * 8 + warp;
    const size_t base = (size_t)row * NND;
    float s = 0.0f;
#pragma unroll
    for (int t = 0; t < 16; ++t)
        s += H[base + lane + t * 32] * W_out[lane + t * 32];
#pragma unroll
    for (int off = 16; off > 0; off >>= 1)
        s += __shfl_down_sync(0xffffffffu, s, off);
    if (lane == 0) out[row] = fsilu(s + b_out[0]);
}

// ================= launch =================
extern "C" void kernel_launch(void* const* d_in, const int* in_sizes, int n_in,
                              void* d_out, int out_size)
{
    const float* X     = (const float*)d_in[0];
    const float* W_in  = (const float*)d_in[1];
    const float* b_in  = (const float*)d_in[2];
    const float* Wf    = (const float*)d_in[3];
    const float* Uf    = (const float*)d_in[4];
    const float* bfp   = (const float*)d_in[5];
    const float* Wu    = (const float*)d_in[6];
    const float* Uu    = (const float*)d_in[7];
    const float* bup   = (const float*)d_in[8];
    const float* Wo1   = (const float*)d_in[9];
    const float* Uo1   = (const float*)d_in[10];
    const float* bo1   = (const float*)d_in[11];
    const float* Wo2   = (const float*)d_in[12];
    const float* bo2   = (const float*)d_in[13];
    const float* W_out = (const float*)d_in[14];
    const float* b_out = (const float*)d_in[15];

    k_init<<<(BATCH * NND) / 256, 256>>>(X, W_in, b_in);

    for (int l = 0; l < NLAYER; ++l) {
        const size_t wOff = (size_t)l * DIN * NND;       // [L,4,512]
        const size_t uOff = (size_t)l * NND * NND;       // [L,512,512]
        const size_t bOff = (size_t)l * NND;             // [L,1,512]
        k_gate<<<dim3(NND / 64, BATCH / 128), 256>>>(
            l, X,
            Wf + wOff, Uf + uOff, bfp + bOff,
            Wu + wOff, Uu + uOff, bup + bOff,
            Wo1 + wOff, Uo1 + uOff, bo1 + bOff);
        k_gemm2<<<dim3(NND / 128, BATCH / 128), 256>>>(
            l, Wo2 + uOff, bo2 + bOff);
    }

    k_out<<<BATCH / 8, 256>>>(W_out, b_out, (float*)d_out);
}

// round 5
// speedup vs baseline: 2.1728x; 2.1728x over previous
#include <cuda_runtime.h>
#include <cstdint>

#define BATCH  131072
#define NND    512
#define NLAYER 3
#define NC     16          // 512 / 32 K-chunks
#define AST    36          // padded smem row stride (floats)

// ---------------- scratch (device globals; no allocation allowed) ----------------
__device__ float g_H0[(size_t)BATCH * NND];
__device__ float g_H1[(size_t)BATCH * NND];
__device__ float g_F [(size_t)BATCH * NND];
__device__ float g_P [(size_t)BATCH * NND];
// transposed weights (tf32-rounded): [layer][gate: Uf,Uu,Uo1,Wo2][j][k]
__device__ float g_UT[(size_t)NLAYER * 4 * NND * NND];

// ---------------- PTX helpers ----------------
__device__ __forceinline__ uint32_t smem_to_u32(const void* p) {
    uint32_t a;
    asm("{ .reg .u64 t; cvta.to.shared.u64 t, %1; cvt.u32.u64 %0, t; }" : "=r"(a) : "l"(p));
    return a;
}
__device__ __forceinline__ void cp_async16(uint32_t dst, const float* src) {
    asm volatile("cp.async.cg.shared.global [%0], [%1], 16;"
                 :: "r"(dst), "l"((unsigned long long)__cvta_generic_to_global((void*)src)) : "memory");
}
__device__ __forceinline__ void cp_commit() {
    asm volatile("cp.async.commit_group;" ::: "memory");
}
template <int N> __device__ __forceinline__ void cp_wait_group() {
    asm volatile("cp.async.wait_group %0;" :: "n"(N) : "memory");
}
// round fp32 -> tf32 (round-to-nearest) so mma.sync inputs are exact
__device__ __forceinline__ float tf32r(float x) {
    uint32_t u;
    asm("cvt.rna.tf32.f32 %0, %1;" : "=r"(u) : "f"(x));
    return __uint_as_float(u);
}
// D += A(16x8,row) * B(8x8,col); tf32 inputs, fp32 accum
__device__ __forceinline__ void mma8(float* c, const uint32_t* a, uint32_t b0, uint32_t b1) {
    asm volatile(
        "mma.sync.aligned.m16n8k8.row.col.f32.tf32.tf32.f32 "
        "{%0,%1,%2,%3},{%4,%5,%6,%7},{%8,%9},{%0,%1,%2,%3};"
        : "+f"(c[0]), "+f"(c[1]), "+f"(c[2]), "+f"(c[3])
        : "r"(a[0]), "r"(a[1]), "r"(a[2]), "r"(a[3]), "r"(b0), "r"(b1));
}

// ---------------- activations ----------------
__device__ __forceinline__ float fsigmoid(float x) { return __fdividef(1.0f, 1.0f + __expf(-x)); }
__device__ __forceinline__ float ftanh_(float x)   { return 1.0f - __fdividef(2.0f, __expf(2.0f * x) + 1.0f); }
__device__ __forceinline__ float fsilu(float x)    { return x * fsigmoid(x); }

// ================= weight transpose (tf32-rounded): g_UT[l][g][j][k] = W[l][g][k][j] =================
__global__ __launch_bounds__(256) void k_transpose(
    const float* __restrict__ Uf, const float* __restrict__ Uu,
    const float* __restrict__ Uo1, const float* __restrict__ Wo2)
{
    __shared__ float t[32][33];
    int mat = blockIdx.z;
    int l = mat >> 2, g = mat & 3;
    const float* srcs[4] = {Uf, Uu, Uo1, Wo2};
    const float* src = srcs[g] + (size_t)l * NND * NND;
    float* dst = g_UT + (size_t)mat * NND * NND;
    int x0 = blockIdx.x * 32, y0 = blockIdx.y * 32;
    int tx = threadIdx.x & 31, ty = threadIdx.x >> 5;
#pragma unroll
    for (int i = 0; i < 4; ++i)
        t[ty + 8 * i][tx] = src[(size_t)(y0 + ty + 8 * i) * NND + x0 + tx];
    __syncthreads();
#pragma unroll
    for (int i = 0; i < 4; ++i)
        dst[(size_t)(x0 + ty + 8 * i) * NND + y0 + tx] = tf32r(t[tx][ty + 8 * i]);
}

// ================= kernel 1: H = tf32(silu(X @ W_in + b_in)) =================
__global__ __launch_bounds__(256) void k_init(
    const float* __restrict__ X, const float* __restrict__ W_in, const float* __restrict__ b_in)
{
    int idx = blockIdx.x * 256 + threadIdx.x;
    int m = idx >> 9;
    int j = idx & (NND - 1);
    float4 xv = reinterpret_cast<const float4*>(X)[m];
    float a = b_in[j] + xv.x * W_in[j] + xv.y * W_in[NND + j]
            + xv.z * W_in[2 * NND + j] + xv.w * W_in[3 * NND + j];
    g_H0[idx] = tf32r(fsilu(a));
}

// ================= gate GEMM (tf32 mma.sync) =================
// grid (8, 1024): x = 64-col j-block, y = 128-row m-block. 256 threads = 8 warps (4x2).
// pre_g = H@U_g^T for g in {f,u,o1}; epilogue adds X@W_g + b_g,
// writes F = sigmoid(pre_f), P = tf32(sigmoid(pre_u)*tanh(pre_o1)).
__global__ __launch_bounds__(256, 1) void k_gate_tc(
    int layer, const float* __restrict__ X,
    const float* __restrict__ Wf_, const float* __restrict__ bf_,
    const float* __restrict__ Wu_, const float* __restrict__ bu_,
    const float* __restrict__ Wo_, const float* __restrict__ bo_)
{
    extern __shared__ float sm[];
    float* As  = sm;                       // 2 stages x 128 x AST = 9216
    float* Bs  = sm + 9216;                // 2 x 3 x 64 x AST = 13824
    float* sW  = sm + 9216 + 13824;        // 3 gates x 4 dims x 64 = 768
    float* sBi = sW + 768;                 // 3 x 64 = 192
    float4* Xs = (float4*)(sBi + 192);     // 128 float4

    const int tid = threadIdx.x;
    const int lane = tid & 31;
    const int wid = tid >> 5;
    const int wM = wid & 3;                // warp row: 32 rows
    const int wN = wid >> 2;               // warp col: 32 cols
    const int gid = lane >> 2;
    const int tig = lane & 3;
    const int m0 = blockIdx.y * 128;
    const int j0 = blockIdx.x * 64;

    const float* __restrict__ Hin = (layer & 1) ? g_H1 : g_H0;
    const float* __restrict__ UT  = g_UT + (size_t)(layer * 4) * NND * NND;

    const uint32_t aBase = smem_to_u32(As);
    const uint32_t bBase = smem_to_u32(Bs);

    // preload W (3 gates x 4 x 64), biases, X rows
    for (int o = tid; o < 768; o += 256) {
        int g = o >> 8, rem = o & 255, d = rem >> 6, jl = rem & 63;
        const float* Wsrc = (g == 0) ? Wf_ : ((g == 1) ? Wu_ : Wo_);
        sW[o] = Wsrc[d * NND + j0 + jl];
    }
    if (tid < 192) {
        int g = tid >> 6, jl = tid & 63;
        sBi[tid] = ((g == 0) ? bf_ : ((g == 1) ? bu_ : bo_))[j0 + jl];
    }
    if (tid < 128) Xs[tid] = reinterpret_cast<const float4*>(X)[m0 + tid];

    float acc[3][2][4][4];
#pragma unroll
    for (int g = 0; g < 3; ++g)
#pragma unroll
        for (int mt = 0; mt < 2; ++mt)
#pragma unroll
            for (int nt = 0; nt < 4; ++nt)
#pragma unroll
                for (int q = 0; q < 4; ++q) acc[g][mt][nt][q] = 0.0f;

    auto loadA = [&](int s, int c) {
        const int k0 = c * 32;
#pragma unroll
        for (int i = 0; i < 4; ++i) {
            int e = tid + 256 * i, r = e >> 3, cc = e & 7;
            cp_async16(aBase + (s * 4608 + r * AST) * 4 + cc * 16,
                       Hin + (size_t)(m0 + r) * NND + k0 + cc * 4);
        }
    };
    auto loadB = [&](int s, int c) {
        const int k0 = c * 32;
#pragma unroll
        for (int i = 0; i < 6; ++i) {
            int e = tid + 256 * i, g = e >> 9, rem = e & 511, r = rem >> 3, cc = rem & 7;
            cp_async16(bBase + ((s * 3 + g) * 2304 + r * AST) * 4 + cc * 16,
                       UT + (size_t)g * NND * NND + (size_t)(j0 + r) * NND + k0 + cc * 4);
        }
    };

    loadA(0, 0); loadB(0, 0); cp_commit();

#pragma unroll 1
    for (int c = 0; c < NC; ++c) {
        const int s = c & 1;
        if (c + 1 < NC) {
            loadA(1 - s, c + 1); loadB(1 - s, c + 1); cp_commit();
            cp_wait_group<1>();
        } else {
            cp_wait_group<0>();
        }
        __syncthreads();

        const float* A_s = As + s * 4608;
#pragma unroll
        for (int ks = 0; ks < 4; ++ks) {
            const int k0 = ks * 8;
            uint32_t a[2][4];
#pragma unroll
            for (int mt = 0; mt < 2; ++mt) {
                int r0 = wM * 32 + mt * 16 + gid;
                a[mt][0] = __float_as_uint(A_s[r0 * AST + k0 + tig]);
                a[mt][1] = __float_as_uint(A_s[(r0 + 8) * AST + k0 + tig]);
                a[mt][2] = __float_as_uint(A_s[r0 * AST + k0 + tig + 4]);
                a[mt][3] = __float_as_uint(A_s[(r0 + 8) * AST + k0 + tig + 4]);
            }
#pragma unroll
            for (int g = 0; g < 3; ++g) {
                const float* B_s = Bs + (s * 3 + g) * 2304;
#pragma unroll
                for (int nt = 0; nt < 4; ++nt) {
                    int n0 = wN * 32 + nt * 8 + gid;
                    uint32_t b0 = __float_as_uint(B_s[n0 * AST + k0 + tig]);
                    uint32_t b1 = __float_as_uint(B_s[n0 * AST + k0 + tig + 4]);
                    mma8(acc[g][0][nt], a[0], b0, b1);
                    mma8(acc[g][1][nt], a[1], b0, b1);
                }
            }
        }
        __syncthreads();
    }

    // -------- epilogue --------
#pragma unroll
    for (int mt = 0; mt < 2; ++mt) {
        int rbase = wM * 32 + mt * 16 + gid;
#pragma unroll
        for (int rr = 0; rr < 2; ++rr) {
            int rloc = rbase + rr * 8;
            int m = m0 + rloc;
            float4 xv = Xs[rloc];
#pragma unroll
            for (int nt = 0; nt < 4; ++nt) {
                int jl = wN * 32 + nt * 8 + 2 * tig;
                float2 Fo, Po;
#pragma unroll
                for (int cc = 0; cc < 2; ++cc) {
                    int j = jl + cc;
                    float fpre = acc[0][mt][nt][rr * 2 + cc] + sBi[j]
                               + xv.x * sW[j]        + xv.y * sW[64 + j]
                               + xv.z * sW[128 + j]  + xv.w * sW[192 + j];
                    float upre = acc[1][mt][nt][rr * 2 + cc] + sBi[64 + j]
                               + xv.x * sW[256 + j]  + xv.y * sW[320 + j]
                               + xv.z * sW[384 + j]  + xv.w * sW[448 + j];
                    float opre = acc[2][mt][nt][rr * 2 + cc] + sBi[128 + j]
                               + xv.x * sW[512 + j]  + xv.y * sW[576 + j]
                               + xv.z * sW[640 + j]  + xv.w * sW[704 + j];
                    float fv = fsigmoid(fpre);
                    float pv = tf32r(fsigmoid(upre) * ftanh_(opre));
                    if (cc == 0) { Fo.x = fv; Po.x = pv; } else { Fo.y = fv; Po.y = pv; }
                }
                *reinterpret_cast<float2*>(&g_F[(size_t)m * NND + j0 + jl]) = Fo;
                *reinterpret_cast<float2*>(&g_P[(size_t)m * NND + j0 + jl]) = Po;
            }
        }
    }
}

// ================= second GEMM (tf32 mma.sync): H_new = F*H + silu(P @ Wo2^T + bo2) =================
// grid (4, 1024): x = 128-col j-block, y = 128-row m-block. 8 warps (4x2), warp tile 32x64.
__global__ __launch_bounds__(256, 1) void k_gemm2_tc(
    int layer, const float* __restrict__ b2)
{
    extern __shared__ float sm[];
    float* As  = sm;                 // 2 x 128 x AST = 9216
    float* Bs  = sm + 9216;          // 2 x 128 x AST = 9216
    float* sBi = sm + 18432;         // 128

    const int tid = threadIdx.x;
    const int lane = tid & 31;
    const int wid = tid >> 5;
    const int wM = wid & 3;
    const int wN = wid >> 2;         // 64 cols per warp
    const int gid = lane >> 2;
    const int tig = lane & 3;
    const int m0 = blockIdx.y * 128;
    const int j0 = blockIdx.x * 128;

    const float* __restrict__ Hin  = (layer & 1) ? g_H1 : g_H0;
    float* __restrict__       Hout = (layer & 1) ? g_H0 : g_H1;
    const float* __restrict__ WT = g_UT + (size_t)(layer * 4 + 3) * NND * NND;

    const uint32_t aBase = smem_to_u32(As);
    const uint32_t bBase = smem_to_u32(Bs);

    if (tid < 128) sBi[tid] = b2[j0 + tid];

    float acc[2][8][4];
#pragma unroll
    for (int mt = 0; mt < 2; ++mt)
#pragma unroll
        for (int nt = 0; nt < 8; ++nt)
#pragma unroll
            for (int q = 0; q < 4; ++q) acc[mt][nt][q] = 0.0f;

    auto loadA = [&](int s, int c) {
        const int k0 = c * 32;
#pragma unroll
        for (int i = 0; i < 4; ++i) {
            int e = tid + 256 * i, r = e >> 3, cc = e & 7;
            cp_async16(aBase + (s * 4608 + r * AST) * 4 + cc * 16,
                       g_P + (size_t)(m0 + r) * NND + k0 + cc * 4);
        }
    };
    auto loadB = [&](int s, int c) {
        const int k0 = c * 32;
#pragma unroll
        for (int i = 0; i < 4; ++i) {
            int e = tid + 256 * i, r = e >> 3, cc = e & 7;
            cp_async16(bBase + (s * 4608 + r * AST) * 4 + cc * 16,
                       WT + (size_t)(j0 + r) * NND + k0 + cc * 4);
        }
    };

    loadA(0, 0); loadB(0, 0); cp_commit();

#pragma unroll 1
    for (int c = 0; c < NC; ++c) {
        const int s = c & 1;
        if (c + 1 < NC) {
            loadA(1 - s, c + 1); loadB(1 - s, c + 1); cp_commit();
            cp_wait_group<1>();
        } else {
            cp_wait_group<0>();
        }
        __syncthreads();

        const float* A_s = As + s * 4608;
        const float* B_s = Bs + s * 4608;
#pragma unroll
        for (int ks = 0; ks < 4; ++ks) {
            const int k0 = ks * 8;
            uint32_t a[2][4];
#pragma unroll
            for (int mt = 0; mt < 2; ++mt) {
                int r0 = wM * 32 + mt * 16 + gid;
                a[mt][0] = __float_as_uint(A_s[r0 * AST + k0 + tig]);
                a[mt][1] = __float_as_uint(A_s[(r0 + 8) * AST + k0 + tig]);
                a[mt][2] = __float_as_uint(A_s[r0 * AST + k0 + tig + 4]);
                a[mt][3] = __float_as_uint(A_s[(r0 + 8) * AST + k0 + tig + 4]);
            }
#pragma unroll
            for (int nt = 0; nt < 8; ++nt) {
                int n0 = wN * 64 + nt * 8 + gid;
                uint32_t b0 = __float_as_uint(B_s[n0 * AST + k0 + tig]);
                uint32_t b1 = __float_as_uint(B_s[n0 * AST + k0 + tig + 4]);
                mma8(acc[0][nt], a[0], b0, b1);
                mma8(acc[1][nt], a[1], b0, b1);
            }
        }
        __syncthreads();
    }

    // -------- epilogue: H_new = F*H + silu(acc + bias), tf32-rounded --------
#pragma unroll
    for (int mt = 0; mt < 2; ++mt) {
        int rbase = wM * 32 + mt * 16 + gid;
#pragma unroll
        for (int rr = 0; rr < 2; ++rr) {
            int m = m0 + rbase + rr * 8;
#pragma unroll
            for (int nt = 0; nt < 8; ++nt) {
                int jl = wN * 64 + nt * 8 + 2 * tig;
                size_t ga = (size_t)m * NND + j0 + jl;
                float2 Fv = *reinterpret_cast<const float2*>(&g_F[ga]);
                float2 Hv = *reinterpret_cast<const float2*>(&Hin[ga]);
                float2 Ho;
                Ho.x = tf32r(Fv.x * Hv.x + fsilu(acc[mt][nt][rr * 2 + 0] + sBi[jl]));
                Ho.y = tf32r(Fv.y * Hv.y + fsilu(acc[mt][nt][rr * 2 + 1] + sBi[jl + 1]));
                *reinterpret_cast<float2*>(&Hout[ga]) = Ho;
            }
        }
    }
}

// ================= kernel 4: out = silu(H @ W_out + b_out) =================
__global__ __launch_bounds__(256) void k_out(
    const float* __restrict__ W_out, const float* __restrict__ b_out, float* __restrict__ out)
{
    const float* __restrict__ H = g_H1;   // after 3 layers: H0->H1->H0->H1
    const int warp = threadIdx.x >> 5;
    const int lane = threadIdx.x & 31;
    const int row = blockIdx.x * 8 + warp;
    const size_t base = (size_t)row * NND;
    float s = 0.0f;
#pragma unroll
    for (int t = 0; t < 16; ++t)
        s += H[base + lane + t * 32] * W_out[lane + t * 32];
#pragma unroll
    for (int off = 16; off > 0; off >>= 1)
        s += __shfl_down_sync(0xffffffffu, s, off);
    if (lane == 0) out[row] = fsilu(s + b_out[0]);
}

// ================= launch =================
extern "C" void kernel_launch(void* const* d_in, const int* in_sizes, int n_in,
                              void* d_out, int out_size)
{
    const float* X     = (const float*)d_in[0];
    const float* W_in  = (const float*)d_in[1];
    const float* b_in  = (const float*)d_in[2];
    const float* Wf    = (const float*)d_in[3];
    const float* Uf    = (const float*)d_in[4];
    const float* bfp   = (const float*)d_in[5];
    const float* Wu    = (const float*)d_in[6];
    const float* Uu    = (const float*)d_in[7];
    const float* bup   = (const float*)d_in[8];
    const float* Wo1   = (const float*)d_in[9];
    const float* Uo1   = (const float*)d_in[10];
    const float* bo1   = (const float*)d_in[11];
    const float* Wo2   = (const float*)d_in[12];
    const float* bo2   = (const float*)d_in[13];
    const float* W_out = (const float*)d_in[14];
    const float* b_out = (const float*)d_in[15];

    const int SMEM_GATE  = 98048;    // (9216+13824+768+192+512) floats
    const int SMEM_GEMM2 = 74240;    // (9216+9216+128) floats
    cudaFuncSetAttribute(k_gate_tc,  cudaFuncAttributeMaxDynamicSharedMemorySize, SMEM_GATE);
    cudaFuncSetAttribute(k_gemm2_tc, cudaFuncAttributeMaxDynamicSharedMemorySize, SMEM_GEMM2);

    k_transpose<<<dim3(16, 16, NLAYER * 4), 256>>>(Uf, Uu, Uo1, Wo2);
    k_init<<<(BATCH * NND) / 256, 256>>>(X, W_in, b_in);

    for (int l = 0; l < NLAYER; ++l) {
        const size_t w4 = (size_t)l * 4 * NND;     // [L,4,512] slice
        const size_t b1 = (size_t)l * NND;         // [L,1,512] slice
        k_gate_tc<<<dim3(8, BATCH / 128), 256, SMEM_GATE>>>(
            l, X,
            Wf + w4, bfp + b1,
            Wu + w4, bup + b1,
            Wo1 + w4, bo1 + b1);
        k_gemm2_tc<<<dim3(4, BATCH / 128), 256, SMEM_GEMM2>>>(l, bo2 + b1);
    }

    k_out<<<BATCH / 8, 256>>>(W_out, b_out, (float*)d_out);
}

// round 6
// speedup vs baseline: 2.2228x; 1.0230x over previous
#include <cuda_runtime.h>
#include <cstdint>

#define BATCH  131072
#define NND    512
#define NLAYER 3
#define NC     16          // 512 / 32 K-chunks
#define AST    36          // padded smem row stride (floats); 144B = 9*16, LDSM conflict-free

// ---------------- scratch (device globals; no allocation allowed) ----------------
__device__ float g_H0[(size_t)BATCH * NND];
__device__ float g_H1[(size_t)BATCH * NND];
__device__ float g_F [(size_t)BATCH * NND];
__device__ float g_P [(size_t)BATCH * NND];
// transposed weights (tf32-rounded): [layer][gate: Uf,Uu,Uo1,Wo2][j][k]
__device__ float g_UT[(size_t)NLAYER * 4 * NND * NND];

// ---------------- PTX helpers ----------------
__device__ __forceinline__ uint32_t smem_to_u32(const void* p) {
    uint32_t a;
    asm("{ .reg .u64 t; cvta.to.shared.u64 t, %1; cvt.u32.u64 %0, t; }" : "=r"(a) : "l"(p));
    return a;
}
__device__ __forceinline__ void cp_async16(uint32_t dst, const float* src) {
    asm volatile("cp.async.cg.shared.global [%0], [%1], 16;"
                 :: "r"(dst), "l"((unsigned long long)__cvta_generic_to_global((void*)src)) : "memory");
}
__device__ __forceinline__ void cp_commit() {
    asm volatile("cp.async.commit_group;" ::: "memory");
}
template <int N> __device__ __forceinline__ void cp_wait_group() {
    asm volatile("cp.async.wait_group %0;" :: "n"(N) : "memory");
}
// round fp32 -> tf32 (round-to-nearest) so mma.sync inputs are exact
__device__ __forceinline__ float tf32r(float x) {
    uint32_t u;
    asm("cvt.rna.tf32.f32 %0, %1;" : "=r"(u) : "f"(x));
    return __uint_as_float(u);
}
// D += A(16x8,row) * B(8x8,col); tf32 inputs, fp32 accum
__device__ __forceinline__ void mma8(float* c, const uint32_t* a, uint32_t b0, uint32_t b1) {
    asm volatile(
        "mma.sync.aligned.m16n8k8.row.col.f32.tf32.tf32.f32 "
        "{%0,%1,%2,%3},{%4,%5,%6,%7},{%8,%9},{%0,%1,%2,%3};"
        : "+f"(c[0]), "+f"(c[1]), "+f"(c[2]), "+f"(c[3])
        : "r"(a[0]), "r"(a[1]), "r"(a[2]), "r"(a[3]), "r"(b0), "r"(b1));
}
// ldmatrix x4 (b16 view of tf32 data): 4 regs out, lane supplies one row address
__device__ __forceinline__ void ldsm4(uint32_t* r, uint32_t addr) {
    asm volatile("ldmatrix.sync.aligned.m8n8.x4.shared.b16 {%0,%1,%2,%3}, [%4];"
        : "=r"(r[0]), "=r"(r[1]), "=r"(r[2]), "=r"(r[3]) : "r"(addr));
}

// ---------------- activations ----------------
__device__ __forceinline__ float fsigmoid(float x) { return __fdividef(1.0f, 1.0f + __expf(-x)); }
__device__ __forceinline__ float ftanh_(float x)   { return 1.0f - __fdividef(2.0f, __expf(2.0f * x) + 1.0f); }
__device__ __forceinline__ float fsilu(float x)    { return x * fsigmoid(x); }

// ================= weight transpose (tf32-rounded): g_UT[l][g][j][k] = W[l][g][k][j] =================
__global__ __launch_bounds__(256) void k_transpose(
    const float* __restrict__ Uf, const float* __restrict__ Uu,
    const float* __restrict__ Uo1, const float* __restrict__ Wo2)
{
    __shared__ float t[32][33];
    int mat = blockIdx.z;
    int l = mat >> 2, g = mat & 3;
    const float* srcs[4] = {Uf, Uu, Uo1, Wo2};
    const float* src = srcs[g] + (size_t)l * NND * NND;
    float* dst = g_UT + (size_t)mat * NND * NND;
    int x0 = blockIdx.x * 32, y0 = blockIdx.y * 32;
    int tx = threadIdx.x & 31, ty = threadIdx.x >> 5;
#pragma unroll
    for (int i = 0; i < 4; ++i)
        t[ty + 8 * i][tx] = src[(size_t)(y0 + ty + 8 * i) * NND + x0 + tx];
    __syncthreads();
#pragma unroll
    for (int i = 0; i < 4; ++i)
        dst[(size_t)(x0 + ty + 8 * i) * NND + y0 + tx] = tf32r(t[tx][ty + 8 * i]);
}

// ================= kernel 1: H = tf32(silu(X @ W_in + b_in)) =================
__global__ __launch_bounds__(256) void k_init(
    const float* __restrict__ X, const float* __restrict__ W_in, const float* __restrict__ b_in)
{
    int idx = blockIdx.x * 256 + threadIdx.x;
    int m = idx >> 9;
    int j = idx & (NND - 1);
    float4 xv = reinterpret_cast<const float4*>(X)[m];
    float a = b_in[j] + xv.x * W_in[j] + xv.y * W_in[NND + j]
            + xv.z * W_in[2 * NND + j] + xv.w * W_in[3 * NND + j];
    g_H0[idx] = tf32r(fsilu(a));
}

// ================= gate GEMM (tf32 mma.sync + ldmatrix, 3-stage pipe) =================
// grid (8, 1024): x = 64-col j-block, y = 128-row m-block. 8 warps (4x2), warp 32x32 per gate.
__global__ __launch_bounds__(256, 1) void k_gate_tc(
    int layer, const float* __restrict__ X,
    const float* __restrict__ Wf_, const float* __restrict__ bf_,
    const float* __restrict__ Wu_, const float* __restrict__ bu_,
    const float* __restrict__ Wo_, const float* __restrict__ bo_)
{
    extern __shared__ float sm[];
    // [stage][A 128xAST | B 3x64xAST] : per stage 4608 + 6912 floats
    float* As  = sm;                        // 3 x 4608
    float* Bs  = sm + 3 * 4608;             // 3 x 3 x 2304
    float* sW  = sm + 3 * 11520;            // 768
    float* sBi = sW + 768;                  // 192
    float4* Xs = (float4*)(sBi + 192);      // 128

    const int tid = threadIdx.x;
    const int lane = tid & 31;
    const int wid = tid >> 5;
    const int wM = wid & 3;
    const int wN = wid >> 2;
    const int gid = lane >> 2;
    const int tig = lane & 3;
    const int m0 = blockIdx.y * 128;
    const int j0 = blockIdx.x * 64;

    const float* __restrict__ Hin = (layer & 1) ? g_H1 : g_H0;
    const float* __restrict__ UT  = g_UT + (size_t)(layer * 4) * NND * NND;

    const uint32_t aBase = smem_to_u32(As);
    const uint32_t bBase = smem_to_u32(Bs);

    // per-lane LDSM tile-row offsets (bytes, within a stage)
    const int lr = lane & 7;
    // A fragment (16 rows x 8 k): 4 tiles = (row-half, k-half)
    uint32_t aoff[2];
#pragma unroll
    for (int mt = 0; mt < 2; ++mt)
        aoff[mt] = (uint32_t)((wM * 32 + mt * 16 + lr + ((lane >> 3) & 1) * 8) * AST * 4
                              + (lane >> 4) * 16);
    // B pair fragment (16 n-rows x 8 k): tiles = (n-half, k-half)
    uint32_t boff[2];
#pragma unroll
    for (int p = 0; p < 2; ++p)
        boff[p] = (uint32_t)((wN * 32 + p * 16 + (lane >> 4) * 8 + lr) * AST * 4
                             + ((lane >> 3) & 1) * 16);

    // preload W (3 gates x 4 x 64), biases, X rows
    for (int o = tid; o < 768; o += 256) {
        int g = o >> 8, rem = o & 255, d = rem >> 6, jl = rem & 63;
        const float* Wsrc = (g == 0) ? Wf_ : ((g == 1) ? Wu_ : Wo_);
        sW[o] = Wsrc[d * NND + j0 + jl];
    }
    if (tid < 192) {
        int g = tid >> 6, jl = tid & 63;
        sBi[tid] = ((g == 0) ? bf_ : ((g == 1) ? bu_ : bo_))[j0 + jl];
    }
    if (tid < 128) Xs[tid] = reinterpret_cast<const float4*>(X)[m0 + tid];

    float acc[3][2][4][4];
#pragma unroll
    for (int g = 0; g < 3; ++g)
#pragma unroll
        for (int mt = 0; mt < 2; ++mt)
#pragma unroll
            for (int nt = 0; nt < 4; ++nt)
#pragma unroll
                for (int q = 0; q < 4; ++q) acc[g][mt][nt][q] = 0.0f;

    auto loadA = [&](int s, int c) {
        const int k0 = c * 32;
#pragma unroll
        for (int i = 0; i < 4; ++i) {
            int e = tid + 256 * i, r = e >> 3, cc = e & 7;
            cp_async16(aBase + (s * 4608 + r * AST) * 4 + cc * 16,
                       Hin + (size_t)(m0 + r) * NND + k0 + cc * 4);
        }
    };
    auto loadB = [&](int s, int c) {
        const int k0 = c * 32;
#pragma unroll
        for (int i = 0; i < 6; ++i) {
            int e = tid + 256 * i, g = e >> 9, rem = e & 511, r = rem >> 3, cc = rem & 7;
            cp_async16(bBase + ((s * 3 + g) * 2304 + r * AST) * 4 + cc * 16,
                       UT + (size_t)g * NND * NND + (size_t)(j0 + r) * NND + k0 + cc * 4);
        }
    };

    loadA(0, 0); loadB(0, 0); cp_commit();
    loadA(1, 1); loadB(1, 1); cp_commit();

#pragma unroll 1
    for (int c = 0; c < NC; ++c) {
        const int s = c % 3;
        if (c + 1 < NC) cp_wait_group<1>(); else cp_wait_group<0>();
        __syncthreads();
        if (c + 2 < NC) {
            const int s2 = (c + 2) % 3;
            loadA(s2, c + 2); loadB(s2, c + 2); cp_commit();
        }
        const uint32_t aS = aBase + (uint32_t)s * 18432;   // 4608*4
        const uint32_t bS = bBase + (uint32_t)(s * 3) * 9216;
#pragma unroll
        for (int ks = 0; ks < 4; ++ks) {
            uint32_t a[2][4];
            ldsm4(a[0], aS + aoff[0] + ks * 32);
            ldsm4(a[1], aS + aoff[1] + ks * 32);
#pragma unroll
            for (int g = 0; g < 3; ++g) {
                const uint32_t bG = bS + (uint32_t)g * 9216;
#pragma unroll
                for (int p = 0; p < 2; ++p) {
                    uint32_t b[4];
                    ldsm4(b, bG + boff[p] + ks * 32);
                    mma8(acc[g][0][2 * p],     a[0], b[0], b[1]);
                    mma8(acc[g][1][2 * p],     a[1], b[0], b[1]);
                    mma8(acc[g][0][2 * p + 1], a[0], b[2], b[3]);
                    mma8(acc[g][1][2 * p + 1], a[1], b[2], b[3]);
                }
            }
        }
    }

    // -------- epilogue --------
#pragma unroll
    for (int mt = 0; mt < 2; ++mt) {
        int rbase = wM * 32 + mt * 16 + gid;
#pragma unroll
        for (int rr = 0; rr < 2; ++rr) {
            int rloc = rbase + rr * 8;
            int m = m0 + rloc;
            float4 xv = Xs[rloc];
#pragma unroll
            for (int nt = 0; nt < 4; ++nt) {
                int jl = wN * 32 + nt * 8 + 2 * tig;
                float2 Fo, Po;
#pragma unroll
                for (int cc = 0; cc < 2; ++cc) {
                    int j = jl + cc;
                    float fpre = acc[0][mt][nt][rr * 2 + cc] + sBi[j]
                               + xv.x * sW[j]        + xv.y * sW[64 + j]
                               + xv.z * sW[128 + j]  + xv.w * sW[192 + j];
                    float upre = acc[1][mt][nt][rr * 2 + cc] + sBi[64 + j]
                               + xv.x * sW[256 + j]  + xv.y * sW[320 + j]
                               + xv.z * sW[384 + j]  + xv.w * sW[448 + j];
                    float opre = acc[2][mt][nt][rr * 2 + cc] + sBi[128 + j]
                               + xv.x * sW[512 + j]  + xv.y * sW[576 + j]
                               + xv.z * sW[640 + j]  + xv.w * sW[704 + j];
                    float fv = fsigmoid(fpre);
                    float pv = tf32r(fsigmoid(upre) * ftanh_(opre));
                    if (cc == 0) { Fo.x = fv; Po.x = pv; } else { Fo.y = fv; Po.y = pv; }
                }
                *reinterpret_cast<float2*>(&g_F[(size_t)m * NND + j0 + jl]) = Fo;
                *reinterpret_cast<float2*>(&g_P[(size_t)m * NND + j0 + jl]) = Po;
            }
        }
    }
}

// ================= second GEMM: H_new = F*H + silu(P @ Wo2^T + bo2) =================
// grid (4, 1024): 8 warps (4x2), warp tile 32x64, ldmatrix + 3-stage pipe.
__global__ __launch_bounds__(256, 1) void k_gemm2_tc(
    int layer, const float* __restrict__ b2)
{
    extern __shared__ float sm[];
    float* As  = sm;                 // 3 x 4608
    float* Bs  = sm + 3 * 4608;      // 3 x 4608
    float* sBi = sm + 6 * 4608;      // 128

    const int tid = threadIdx.x;
    const int lane = tid & 31;
    const int wid = tid >> 5;
    const int wM = wid & 3;
    const int wN = wid >> 2;
    const int gid = lane >> 2;
    const int tig = lane & 3;
    const int m0 = blockIdx.y * 128;
    const int j0 = blockIdx.x * 128;

    const float* __restrict__ Hin  = (layer & 1) ? g_H1 : g_H0;
    float* __restrict__       Hout = (layer & 1) ? g_H0 : g_H1;
    const float* __restrict__ WT = g_UT + (size_t)(layer * 4 + 3) * NND * NND;

    const uint32_t aBase = smem_to_u32(As);
    const uint32_t bBase = smem_to_u32(Bs);

    const int lr = lane & 7;
    uint32_t aoff[2];
#pragma unroll
    for (int mt = 0; mt < 2; ++mt)
        aoff[mt] = (uint32_t)((wM * 32 + mt * 16 + lr + ((lane >> 3) & 1) * 8) * AST * 4
                              + (lane >> 4) * 16);
    uint32_t boff[4];
#pragma unroll
    for (int p = 0; p < 4; ++p)
        boff[p] = (uint32_t)((wN * 64 + p * 16 + (lane >> 4) * 8 + lr) * AST * 4
                             + ((lane >> 3) & 1) * 16);

    if (tid < 128) sBi[tid] = b2[j0 + tid];

    float acc[2][8][4];
#pragma unroll
    for (int mt = 0; mt < 2; ++mt)
#pragma unroll
        for (int nt = 0; nt < 8; ++nt)
#pragma unroll
            for (int q = 0; q < 4; ++q) acc[mt][nt][q] = 0.0f;

    auto loadA = [&](int s, int c) {
        const int k0 = c * 32;
#pragma unroll
        for (int i = 0; i < 4; ++i) {
            int e = tid + 256 * i, r = e >> 3, cc = e & 7;
            cp_async16(aBase + (s * 4608 + r * AST) * 4 + cc * 16,
                       g_P + (size_t)(m0 + r) * NND + k0 + cc * 4);
        }
    };
    auto loadB = [&](int s, int c) {
        const int k0 = c * 32;
#pragma unroll
        for (int i = 0; i < 4; ++i) {
            int e = tid + 256 * i, r = e >> 3, cc = e & 7;
            cp_async16(bBase + (s * 4608 + r * AST) * 4 + cc * 16,
                       WT + (size_t)(j0 + r) * NND + k0 + cc * 4);
        }
    };

    loadA(0, 0); loadB(0, 0); cp_commit();
    loadA(1, 1); loadB(1, 1); cp_commit();

#pragma unroll 1
    for (int c = 0; c < NC; ++c) {
        const int s = c % 3;
        if (c + 1 < NC) cp_wait_group<1>(); else cp_wait_group<0>();
        __syncthreads();
        if (c + 2 < NC) {
            const int s2 = (c + 2) % 3;
            loadA(s2, c + 2); loadB(s2, c + 2); cp_commit();
        }
        const uint32_t aS = aBase + (uint32_t)s * 18432;
        const uint32_t bS = bBase + (uint32_t)s * 18432;
#pragma unroll
        for (int ks = 0; ks < 4; ++ks) {
            uint32_t a[2][4];
            ldsm4(a[0], aS + aoff[0] + ks * 32);
            ldsm4(a[1], aS + aoff[1] + ks * 32);
#pragma unroll
            for (int p = 0; p < 4; ++p) {
                uint32_t b[4];
                ldsm4(b, bS + boff[p] + ks * 32);
                mma8(acc[0][2 * p],     a[0], b[0], b[1]);
                mma8(acc[1][2 * p],     a[1], b[0], b[1]);
                mma8(acc[0][2 * p + 1], a[0], b[2], b[3]);
                mma8(acc[1][2 * p + 1], a[1], b[2], b[3]);
            }
        }
    }

    // -------- epilogue: H_new = F*H + silu(acc + bias), tf32-rounded --------
#pragma unroll
    for (int mt = 0; mt < 2; ++mt) {
        int rbase = wM * 32 + mt * 16 + gid;
#pragma unroll
        for (int rr = 0; rr < 2; ++rr) {
            int m = m0 + rbase + rr * 8;
#pragma unroll
            for (int nt = 0; nt < 8; ++nt) {
                int jl = wN * 64 + nt * 8 + 2 * tig;
                size_t ga = (size_t)m * NND + j0 + jl;
                float2 Fv = *reinterpret_cast<const float2*>(&g_F[ga]);
                float2 Hv = *reinterpret_cast<const float2*>(&Hin[ga]);
                float2 Ho;
                Ho.x = tf32r(Fv.x * Hv.x + fsilu(acc[mt][nt][rr * 2 + 0] + sBi[jl]));
                Ho.y = tf32r(Fv.y * Hv.y + fsilu(acc[mt][nt][rr * 2 + 1] + sBi[jl + 1]));
                *reinterpret_cast<float2*>(&Hout[ga]) = Ho;
            }
        }
    }
}

// ================= kernel 4: out = silu(H @ W_out + b_out) =================
__global__ __launch_bounds__(256) void k_out(
    const float* __restrict__ W_out, const float* __restrict__ b_out, float* __restrict__ out)
{
    const float* __restrict__ H = g_H1;   // after 3 layers: H0->H1->H0->H1
    const int warp = threadIdx.x >> 5;
    const int lane = threadIdx.x & 31;
    const int row = blockIdx.x * 8 + warp;
    const size_t base = (size_t)row * NND;
    float s = 0.0f;
#pragma unroll
    for (int t = 0; t < 16; ++t)
        s += H[base + lane + t * 32] * W_out[lane + t * 32];
#pragma unroll
    for (int off = 16; off > 0; off >>= 1)
        s += __shfl_down_sync(0xffffffffu, s, off);
    if (lane == 0) out[row] = fsilu(s + b_out[0]);
}

// ================= launch =================
extern "C" void kernel_launch(void* const* d_in, const int* in_sizes, int n_in,
                              void* d_out, int out_size)
{
    const float* X     = (const float*)d_in[0];
    const float* W_in  = (const float*)d_in[1];
    const float* b_in  = (const float*)d_in[2];
    const float* Wf    = (const float*)d_in[3];
    const float* Uf    = (const float*)d_in[4];
    const float* bfp   = (const float*)d_in[5];
    const float* Wu    = (const float*)d_in[6];
    const float* Uu    = (const float*)d_in[7];
    const float* bup   = (const float*)d_in[8];
    const float* Wo1   = (const float*)d_in[9];
    const float* Uo1   = (const float*)d_in[10];
    const float* bo1   = (const float*)d_in[11];
    const float* Wo2   = (const float*)d_in[12];
    const float* bo2   = (const float*)d_in[13];
    const float* W_out = (const float*)d_in[14];
    const float* b_out = (const float*)d_in[15];

    const int SMEM_GATE  = (3 * 11520 + 768 + 192 + 512) * 4;   // 144128 B
    const int SMEM_GEMM2 = (6 * 4608 + 128) * 4;                // 111104 B
    cudaFuncSetAttribute(k_gate_tc,  cudaFuncAttributeMaxDynamicSharedMemorySize, SMEM_GATE);
    cudaFuncSetAttribute(k_gemm2_tc, cudaFuncAttributeMaxDynamicSharedMemorySize, SMEM_GEMM2);

    k_transpose<<<dim3(16, 16, NLAYER * 4), 256>>>(Uf, Uu, Uo1, Wo2);
    k_init<<<(BATCH * NND) / 256, 256>>>(X, W_in, b_in);

    for (int l = 0; l < NLAYER; ++l) {
        const size_t w4 = (size_t)l * 4 * NND;     // [L,4,512] slice
        const size_t b1 = (size_t)l * NND;         // [L,1,512] slice
        k_gate_tc<<<dim3(8, BATCH / 128), 256, SMEM_GATE>>>(
            l, X,
            Wf + w4, bfp + b1,
            Wu + w4, bup + b1,
            Wo1 + w4, bo1 + b1);
        k_gemm2_tc<<<dim3(4, BATCH / 128), 256, SMEM_GEMM2>>>(l, bo2 + b1);
    }

    k_out<<<BATCH / 8, 256>>>(W_out, b_out, (float*)d_out);
}

// round 7
// speedup vs baseline: 2.2742x; 1.0231x over previous
#include <cuda_runtime.h>
#include <cstdint>

#define BATCH  131072
#define NND    512
#define NLAYER 3
#define NC     16          // 512 / 32 K-chunks
#define AST    36          // padded smem row stride (floats); LDSM conflict-free

// ---------------- scratch (device globals; no allocation allowed) ----------------
__device__ float g_H0[(size_t)BATCH * NND];
__device__ float g_H1[(size_t)BATCH * NND];
__device__ float g_F [(size_t)BATCH * NND];
__device__ float g_P [(size_t)BATCH * NND];
// transposed weights (tf32-rounded): [layer][gate: Uf,Uu,Uo1,Wo2][j][k]
__device__ float g_UT[(size_t)NLAYER * 4 * NND * NND];

// ---------------- PTX helpers ----------------
__device__ __forceinline__ uint32_t smem_to_u32(const void* p) {
    uint32_t a;
    asm("{ .reg .u64 t; cvta.to.shared.u64 t, %1; cvt.u32.u64 %0, t; }" : "=r"(a) : "l"(p));
    return a;
}
__device__ __forceinline__ void cp_async16(uint32_t dst, const float* src) {
    asm volatile("cp.async.cg.shared.global [%0], [%1], 16;"
                 :: "r"(dst), "l"((unsigned long long)__cvta_generic_to_global((void*)src)) : "memory");
}
__device__ __forceinline__ void cp_commit() {
    asm volatile("cp.async.commit_group;" ::: "memory");
}
template <int N> __device__ __forceinline__ void cp_wait_group() {
    asm volatile("cp.async.wait_group %0;" :: "n"(N) : "memory");
}
// round fp32 -> tf32 (round-to-nearest) so mma.sync inputs are exact
__device__ __forceinline__ float tf32r(float x) {
    uint32_t u;
    asm("cvt.rna.tf32.f32 %0, %1;" : "=r"(u) : "f"(x));
    return __uint_as_float(u);
}
// D += A(16x8,row) * B(8x8,col); tf32 inputs, fp32 accum
__device__ __forceinline__ void mma8(float* c, const uint32_t* a, uint32_t b0, uint32_t b1) {
    asm volatile(
        "mma.sync.aligned.m16n8k8.row.col.f32.tf32.tf32.f32 "
        "{%0,%1,%2,%3},{%4,%5,%6,%7},{%8,%9},{%0,%1,%2,%3};"
        : "+f"(c[0]), "+f"(c[1]), "+f"(c[2]), "+f"(c[3])
        : "r"(a[0]), "r"(a[1]), "r"(a[2]), "r"(a[3]), "r"(b0), "r"(b1));
}
// ldmatrix x4 (b16 view of tf32 data)
__device__ __forceinline__ void ldsm4(uint32_t* r, uint32_t addr) {
    asm volatile("ldmatrix.sync.aligned.m8n8.x4.shared.b16 {%0,%1,%2,%3}, [%4];"
        : "=r"(r[0]), "=r"(r[1]), "=r"(r[2]), "=r"(r[3]) : "r"(addr));
}

// ---------------- activations ----------------
__device__ __forceinline__ float fsigmoid(float x) { return __fdividef(1.0f, 1.0f + __expf(-x)); }
__device__ __forceinline__ float ftanh_(float x)   { return 1.0f - __fdividef(2.0f, __expf(2.0f * x) + 1.0f); }
__device__ __forceinline__ float fsilu(float x)    { return x * fsigmoid(x); }

// ================= weight transpose (tf32-rounded): g_UT[l][g][j][k] = W[l][g][k][j] =================
__global__ __launch_bounds__(256) void k_transpose(
    const float* __restrict__ Uf, const float* __restrict__ Uu,
    const float* __restrict__ Uo1, const float* __restrict__ Wo2)
{
    __shared__ float t[32][33];
    int mat = blockIdx.z;
    int l = mat >> 2, g = mat & 3;
    const float* srcs[4] = {Uf, Uu, Uo1, Wo2};
    const float* src = srcs[g] + (size_t)l * NND * NND;
    float* dst = g_UT + (size_t)mat * NND * NND;
    int x0 = blockIdx.x * 32, y0 = blockIdx.y * 32;
    int tx = threadIdx.x & 31, ty = threadIdx.x >> 5;
#pragma unroll
    for (int i = 0; i < 4; ++i)
        t[ty + 8 * i][tx] = src[(size_t)(y0 + ty + 8 * i) * NND + x0 + tx];
    __syncthreads();
#pragma unroll
    for (int i = 0; i < 4; ++i)
        dst[(size_t)(x0 + ty + 8 * i) * NND + y0 + tx] = tf32r(t[tx][ty + 8 * i]);
}

// ================= kernel 1: H = tf32(silu(X @ W_in + b_in)) =================
__global__ __launch_bounds__(256) void k_init(
    const float* __restrict__ X, const float* __restrict__ W_in, const float* __restrict__ b_in)
{
    int idx = blockIdx.x * 256 + threadIdx.x;
    int m = idx >> 9;
    int j = idx & (NND - 1);
    float4 xv = reinterpret_cast<const float4*>(X)[m];
    float a = b_in[j] + xv.x * W_in[j] + xv.y * W_in[NND + j]
            + xv.z * W_in[2 * NND + j] + xv.w * W_in[3 * NND + j];
    g_H0[idx] = tf32r(fsilu(a));
}

// ================= gate GEMM (tf32 mma.sync, 16 warps, 3-stage pipe) =================
// grid (8, 1024): x = 64-col j-block, y = 128-row m-block.
// 512 threads = 16 warps (4M x 4N); warp tile 32(M) x 16(N) per gate.
__global__ __launch_bounds__(512, 1) void k_gate_tc(
    int layer, const float* __restrict__ X,
    const float* __restrict__ Wf_, const float* __restrict__ bf_,
    const float* __restrict__ Wu_, const float* __restrict__ bu_,
    const float* __restrict__ Wo_, const float* __restrict__ bo_)
{
    extern __shared__ float sm[];
    float* As  = sm;                        // 3 x 4608  (128 x AST per stage)
    float* Bs  = sm + 3 * 4608;             // 3 x 3 x 2304 (64 x AST per gate)
    float* sW  = sm + 3 * 11520;            // 768
    float* sBi = sW + 768;                  // 192
    float4* Xs = (float4*)(sBi + 192);      // 128

    const int tid = threadIdx.x;
    const int lane = tid & 31;
    const int wid = tid >> 5;
    const int wM = wid & 3;                 // 32 rows
    const int wN = wid >> 2;                // 16 cols (per gate)
    const int gid = lane >> 2;
    const int tig = lane & 3;
    const int m0 = blockIdx.y * 128;
    const int j0 = blockIdx.x * 64;

    const float* __restrict__ Hin = (layer & 1) ? g_H1 : g_H0;
    const float* __restrict__ UT  = g_UT + (size_t)(layer * 4) * NND * NND;

    const uint32_t aBase = smem_to_u32(As);
    const uint32_t bBase = smem_to_u32(Bs);

    const int lr = lane & 7;
    // A fragment (16x8 x2 halves in k): 2 per warp-row
    uint32_t aoff[2];
#pragma unroll
    for (int mt = 0; mt < 2; ++mt)
        aoff[mt] = (uint32_t)((wM * 32 + mt * 16 + lr + ((lane >> 3) & 1) * 8) * AST * 4
                              + (lane >> 4) * 16);
    // B pair fragment (16 n-rows covering warp's 16 cols)
    const uint32_t boff = (uint32_t)((wN * 16 + (lane >> 4) * 8 + lr) * AST * 4
                                     + ((lane >> 3) & 1) * 16);

    // preload W (3 gates x 4 x 64), biases, X rows
    for (int o = tid; o < 768; o += 512) {
        int g = o >> 8, rem = o & 255, d = rem >> 6, jl = rem & 63;
        const float* Wsrc = (g == 0) ? Wf_ : ((g == 1) ? Wu_ : Wo_);
        sW[o] = Wsrc[d * NND + j0 + jl];
    }
    if (tid < 192) {
        int g = tid >> 6, jl = tid & 63;
        sBi[tid] = ((g == 0) ? bf_ : ((g == 1) ? bu_ : bo_))[j0 + jl];
    }
    if (tid < 128) Xs[tid] = reinterpret_cast<const float4*>(X)[m0 + tid];

    float acc[3][2][2][4];          // [gate][mt][nt(2x8=16 cols)][quad]
#pragma unroll
    for (int g = 0; g < 3; ++g)
#pragma unroll
        for (int mt = 0; mt < 2; ++mt)
#pragma unroll
            for (int nt = 0; nt < 2; ++nt)
#pragma unroll
                for (int q = 0; q < 4; ++q) acc[g][mt][nt][q] = 0.0f;

    auto loadA = [&](int s, int c) {
        const int k0 = c * 32;
#pragma unroll
        for (int i = 0; i < 2; ++i) {
            int e = tid + 512 * i, r = e >> 3, cc = e & 7;
            cp_async16(aBase + (s * 4608 + r * AST) * 4 + cc * 16,
                       Hin + (size_t)(m0 + r) * NND + k0 + cc * 4);
        }
    };
    auto loadB = [&](int s, int c) {
        const int k0 = c * 32;
#pragma unroll
        for (int i = 0; i < 3; ++i) {
            int e = tid + 512 * i, g = e >> 9, rem = e & 511, r = rem >> 3, cc = rem & 7;
            cp_async16(bBase + ((s * 3 + g) * 2304 + r * AST) * 4 + cc * 16,
                       UT + (size_t)g * NND * NND + (size_t)(j0 + r) * NND + k0 + cc * 4);
        }
    };

    loadA(0, 0); loadB(0, 0); cp_commit();
    loadA(1, 1); loadB(1, 1); cp_commit();

#pragma unroll 1
    for (int c = 0; c < NC; ++c) {
        const int s = c % 3;
        if (c + 1 < NC) cp_wait_group<1>(); else cp_wait_group<0>();
        __syncthreads();
        if (c + 2 < NC) {
            const int s2 = (c + 2) % 3;
            loadA(s2, c + 2); loadB(s2, c + 2); cp_commit();
        }
        const uint32_t aS = aBase + (uint32_t)s * 18432;
        const uint32_t bS = bBase + (uint32_t)(s * 3) * 9216;
#pragma unroll
        for (int ks = 0; ks < 4; ++ks) {
            uint32_t a[2][4];
            ldsm4(a[0], aS + aoff[0] + ks * 32);
            ldsm4(a[1], aS + aoff[1] + ks * 32);
#pragma unroll
            for (int g = 0; g < 3; ++g) {
                uint32_t b[4];
                ldsm4(b, bS + (uint32_t)g * 9216 + boff + ks * 32);
                mma8(acc[g][0][0], a[0], b[0], b[1]);
                mma8(acc[g][1][0], a[1], b[0], b[1]);
                mma8(acc[g][0][1], a[0], b[2], b[3]);
                mma8(acc[g][1][1], a[1], b[2], b[3]);
            }
        }
    }

    // -------- epilogue --------
#pragma unroll
    for (int mt = 0; mt < 2; ++mt) {
        int rbase = wM * 32 + mt * 16 + gid;
#pragma unroll
        for (int rr = 0; rr < 2; ++rr) {
            int rloc = rbase + rr * 8;
            int m = m0 + rloc;
            float4 xv = Xs[rloc];
#pragma unroll
            for (int nt = 0; nt < 2; ++nt) {
                int jl = wN * 16 + nt * 8 + 2 * tig;
                float2 Fo, Po;
#pragma unroll
                for (int cc = 0; cc < 2; ++cc) {
                    int j = jl + cc;
                    float fpre = acc[0][mt][nt][rr * 2 + cc] + sBi[j]
                               + xv.x * sW[j]        + xv.y * sW[64 + j]
                               + xv.z * sW[128 + j]  + xv.w * sW[192 + j];
                    float upre = acc[1][mt][nt][rr * 2 + cc] + sBi[64 + j]
                               + xv.x * sW[256 + j]  + xv.y * sW[320 + j]
                               + xv.z * sW[384 + j]  + xv.w * sW[448 + j];
                    float opre = acc[2][mt][nt][rr * 2 + cc] + sBi[128 + j]
                               + xv.x * sW[512 + j]  + xv.y * sW[576 + j]
                               + xv.z * sW[640 + j]  + xv.w * sW[704 + j];
                    float fv = fsigmoid(fpre);
                    float pv = tf32r(fsigmoid(upre) * ftanh_(opre));
                    if (cc == 0) { Fo.x = fv; Po.x = pv; } else { Fo.y = fv; Po.y = pv; }
                }
                *reinterpret_cast<float2*>(&g_F[(size_t)m * NND + j0 + jl]) = Fo;
                *reinterpret_cast<float2*>(&g_P[(size_t)m * NND + j0 + jl]) = Po;
            }
        }
    }
}

// ================= second GEMM: H_new = F*H + silu(P @ Wo2^T + bo2) =================
// grid (4, 1024): 512 threads = 16 warps (4M x 4N), warp tile 32x32.
__global__ __launch_bounds__(512, 1) void k_gemm2_tc(
    int layer, const float* __restrict__ b2)
{
    extern __shared__ float sm[];
    float* As  = sm;                 // 3 x 4608
    float* Bs  = sm + 3 * 4608;      // 3 x 4608
    float* sBi = sm + 6 * 4608;      // 128

    const int tid = threadIdx.x;
    const int lane = tid & 31;
    const int wid = tid >> 5;
    const int wM = wid & 3;
    const int wN = wid >> 2;         // 32 cols
    const int gid = lane >> 2;
    const int tig = lane & 3;
    const int m0 = blockIdx.y * 128;
    const int j0 = blockIdx.x * 128;

    const float* __restrict__ Hin  = (layer & 1) ? g_H1 : g_H0;
    float* __restrict__       Hout = (layer & 1) ? g_H0 : g_H1;
    const float* __restrict__ WT = g_UT + (size_t)(layer * 4 + 3) * NND * NND;

    const uint32_t aBase = smem_to_u32(As);
    const uint32_t bBase = smem_to_u32(Bs);

    const int lr = lane & 7;
    uint32_t aoff[2];
#pragma unroll
    for (int mt = 0; mt < 2; ++mt)
        aoff[mt] = (uint32_t)((wM * 32 + mt * 16 + lr + ((lane >> 3) & 1) * 8) * AST * 4
                              + (lane >> 4) * 16);
    uint32_t boff[2];
#pragma unroll
    for (int p = 0; p < 2; ++p)
        boff[p] = (uint32_t)((wN * 32 + p * 16 + (lane >> 4) * 8 + lr) * AST * 4
                             + ((lane >> 3) & 1) * 16);

    if (tid < 128) sBi[tid] = b2[j0 + tid];

    float acc[2][4][4];
#pragma unroll
    for (int mt = 0; mt < 2; ++mt)
#pragma unroll
        for (int nt = 0; nt < 4; ++nt)
#pragma unroll
            for (int q = 0; q < 4; ++q) acc[mt][nt][q] = 0.0f;

    auto loadA = [&](int s, int c) {
        const int k0 = c * 32;
#pragma unroll
        for (int i = 0; i < 2; ++i) {
            int e = tid + 512 * i, r = e >> 3, cc = e & 7;
            cp_async16(aBase + (s * 4608 + r * AST) * 4 + cc * 16,
                       g_P + (size_t)(m0 + r) * NND + k0 + cc * 4);
        }
    };
    auto loadB = [&](int s, int c) {
        const int k0 = c * 32;
#pragma unroll
        for (int i = 0; i < 2; ++i) {
            int e = tid + 512 * i, r = e >> 3, cc = e & 7;
            cp_async16(bBase + (s * 4608 + r * AST) * 4 + cc * 16,
                       WT + (size_t)(j0 + r) * NND + k0 + cc * 4);
        }
    };

    loadA(0, 0); loadB(0, 0); cp_commit();
    loadA(1, 1); loadB(1, 1); cp_commit();

#pragma unroll 1
    for (int c = 0; c < NC; ++c) {
        const int s = c % 3;
        if (c + 1 < NC) cp_wait_group<1>(); else cp_wait_group<0>();
        __syncthreads();
        if (c + 2 < NC) {
            const int s2 = (c + 2) % 3;
            loadA(s2, c + 2); loadB(s2, c + 2); cp_commit();
        }
        const uint32_t aS = aBase + (uint32_t)s * 18432;
        const uint32_t bS = bBase + (uint32_t)s * 18432;
#pragma unroll
        for (int ks = 0; ks < 4; ++ks) {
            uint32_t a[2][4];
            ldsm4(a[0], aS + aoff[0] + ks * 32);
            ldsm4(a[1], aS + aoff[1] + ks * 32);
#pragma unroll
            for (int p = 0; p < 2; ++p) {
                uint32_t b[4];
                ldsm4(b, bS + boff[p] + ks * 32);
                mma8(acc[0][2 * p],     a[0], b[0], b[1]);
                mma8(acc[1][2 * p],     a[1], b[0], b[1]);
                mma8(acc[0][2 * p + 1], a[0], b[2], b[3]);
                mma8(acc[1][2 * p + 1], a[1], b[2], b[3]);
            }
        }
    }

    // -------- epilogue: H_new = F*H + silu(acc + bias), tf32-rounded --------
#pragma unroll
    for (int mt = 0; mt < 2; ++mt) {
        int rbase = wM * 32 + mt * 16 + gid;
#pragma unroll
        for (int rr = 0; rr < 2; ++rr) {
            int m = m0 + rbase + rr * 8;
#pragma unroll
            for (int nt = 0; nt < 4; ++nt) {
                int jl = wN * 32 + nt * 8 + 2 * tig;
                size_t ga = (size_t)m * NND + j0 + jl;
                float2 Fv = *reinterpret_cast<const float2*>(&g_F[ga]);
                float2 Hv = *reinterpret_cast<const float2*>(&Hin[ga]);
                float2 Ho;
                Ho.x = tf32r(Fv.x * Hv.x + fsilu(acc[mt][nt][rr * 2 + 0] + sBi[jl]));
                Ho.y = tf32r(Fv.y * Hv.y + fsilu(acc[mt][nt][rr * 2 + 1] + sBi[jl + 1]));
                *reinterpret_cast<float2*>(&Hout[ga]) = Ho;
            }
        }
    }
}

// ================= kernel 4: out = silu(H @ W_out + b_out) =================
__global__ __launch_bounds__(256) void k_out(
    const float* __restrict__ W_out, const float* __restrict__ b_out, float* __restrict__ out)
{
    const float* __restrict__ H = g_H1;   // after 3 layers: H0->H1->H0->H1
    const int warp = threadIdx.x >> 5;
    const int lane = threadIdx.x & 31;
    const int row = blockIdx.x * 8 + warp;
    const size_t base = (size_t)row * NND;
    float s = 0.0f;
#pragma unroll
    for (int t = 0; t < 16; ++t)
        s += H[base + lane + t * 32] * W_out[lane + t * 32];
#pragma unroll
    for (int off = 16; off > 0; off >>= 1)
        s += __shfl_down_sync(0xffffffffu, s, off);
    if (lane == 0) out[row] = fsilu(s + b_out[0]);
}

// ================= launch =================
extern "C" void kernel_launch(void* const* d_in, const int* in_sizes, int n_in,
                              void* d_out, int out_size)
{
    const float* X     = (const float*)d_in[0];
    const float* W_in  = (const float*)d_in[1];
    const float* b_in  = (const float*)d_in[2];
    const float* Wf    = (const float*)d_in[3];
    const float* Uf    = (const float*)d_in[4];
    const float* bfp   = (const float*)d_in[5];
    const float* Wu    = (const float*)d_in[6];
    const float* Uu    = (const float*)d_in[7];
    const float* bup   = (const float*)d_in[8];
    const float* Wo1   = (const float*)d_in[9];
    const float* Uo1   = (const float*)d_in[10];
    const float* bo1   = (const float*)d_in[11];
    const float* Wo2   = (const float*)d_in[12];
    const float* bo2   = (const float*)d_in[13];
    const float* W_out = (const float*)d_in[14];
    const float* b_out = (const float*)d_in[15];

    const int SMEM_GATE  = (3 * 11520 + 768 + 192 + 512) * 4;   // 144128 B
    const int SMEM_GEMM2 = (6 * 4608 + 128) * 4;                // 111104 B
    cudaFuncSetAttribute(k_gate_tc,  cudaFuncAttributeMaxDynamicSharedMemorySize, SMEM_GATE);
    cudaFuncSetAttribute(k_gemm2_tc, cudaFuncAttributeMaxDynamicSharedMemorySize, SMEM_GEMM2);

    k_transpose<<<dim3(16, 16, NLAYER * 4), 256>>>(Uf, Uu, Uo1, Wo2);
    k_init<<<(BATCH * NND) / 256, 256>>>(X, W_in, b_in);

    for (int l = 0; l < NLAYER; ++l) {
        const size_t w4 = (size_t)l * 4 * NND;     // [L,4,512] slice
        const size_t b1 = (size_t)l * NND;         // [L,1,512] slice
        k_gate_tc<<<dim3(8, BATCH / 128), 512, SMEM_GATE>>>(
            l, X,
            Wf + w4, bfp + b1,
            Wu + w4, bup + b1,
            Wo1 + w4, bo1 + b1);
        k_gemm2_tc<<<dim3(4, BATCH / 128), 512, SMEM_GEMM2>>>(l, bo2 + b1);
    }

    k_out<<<BATCH / 8, 256>>>(W_out, b_out, (float*)d_out);
}

// round 9
// speedup vs baseline: 3.9077x; 1.7183x over previous
#include <cuda_runtime.h>
#include <cuda_fp16.h>
#include <cstdint>

#define BATCH  131072
#define NND    512
#define NLAYER 3
#define NC     8           // 512 / 64 K-chunks
#define HST    72          // padded smem row stride (halves); 144B, LDSM conflict-free

// ---------------- scratch (device globals; no allocation allowed) ----------------
__device__ __half g_H0[(size_t)BATCH * NND];
__device__ __half g_H1[(size_t)BATCH * NND];
__device__ __half g_F [(size_t)BATCH * NND];
__device__ __half g_P [(size_t)BATCH * NND];
// transposed fp16 weights: [layer][gate: Uf,Uu,Uo1,Wo2][j][k]
__device__ __half g_UT[(size_t)NLAYER * 4 * NND * NND];

// ---------------- PTX helpers ----------------
__device__ __forceinline__ uint32_t smem_to_u32(const void* p) {
    uint32_t a;
    asm("{ .reg .u64 t; cvta.to.shared.u64 t, %1; cvt.u32.u64 %0, t; }" : "=r"(a) : "l"(p));
    return a;
}
__device__ __forceinline__ void cp_async16(uint32_t dst, const void* src) {
    asm volatile("cp.async.cg.shared.global [%0], [%1], 16;"
                 :: "r"(dst), "l"((unsigned long long)__cvta_generic_to_global((void*)src)) : "memory");
}
__device__ __forceinline__ void cp_commit() {
    asm volatile("cp.async.commit_group;" ::: "memory");
}
template <int N> __device__ __forceinline__ void cp_wait_group() {
    asm volatile("cp.async.wait_group %0;" :: "n"(N) : "memory");
}
// D += A(16x16,row) * B(16x8,col); fp16 inputs, fp32 accum
__device__ __forceinline__ void mmaf16(float* c, const uint32_t* a, uint32_t b0, uint32_t b1) {
    asm volatile(
        "mma.sync.aligned.m16n8k16.row.col.f32.f16.f16.f32 "
        "{%0,%1,%2,%3},{%4,%5,%6,%7},{%8,%9},{%0,%1,%2,%3};"
        : "+f"(c[0]), "+f"(c[1]), "+f"(c[2]), "+f"(c[3])
        : "r"(a[0]), "r"(a[1]), "r"(a[2]), "r"(a[3]), "r"(b0), "r"(b1));
}
__device__ __forceinline__ void ldsm4(uint32_t* r, uint32_t addr) {
    asm volatile("ldmatrix.sync.aligned.m8n8.x4.shared.b16 {%0,%1,%2,%3}, [%4];"
        : "=r"(r[0]), "=r"(r[1]), "=r"(r[2]), "=r"(r[3]) : "r"(addr));
}

// ---------------- activations ----------------
__device__ __forceinline__ float fsigmoid(float x) { return __fdividef(1.0f, 1.0f + __expf(-x)); }
__device__ __forceinline__ float ftanh_(float x)   { return 1.0f - __fdividef(2.0f, __expf(2.0f * x) + 1.0f); }
__device__ __forceinline__ float fsilu(float x)    { return x * fsigmoid(x); }

// ================= weight transpose (fp16): g_UT[l][g][j][k] = W[l][g][k][j] =================
__global__ __launch_bounds__(256) void k_transpose(
    const float* __restrict__ Uf, const float* __restrict__ Uu,
    const float* __restrict__ Uo1, const float* __restrict__ Wo2)
{
    __shared__ float t[32][33];
    int mat = blockIdx.z;
    int l = mat >> 2, g = mat & 3;
    const float* srcs[4] = {Uf, Uu, Uo1, Wo2};
    const float* src = srcs[g] + (size_t)l * NND * NND;
    __half* dst = g_UT + (size_t)mat * NND * NND;
    int x0 = blockIdx.x * 32, y0 = blockIdx.y * 32;
    int tx = threadIdx.x & 31, ty = threadIdx.x >> 5;
#pragma unroll
    for (int i = 0; i < 4; ++i)
        t[ty + 8 * i][tx] = src[(size_t)(y0 + ty + 8 * i) * NND + x0 + tx];
    __syncthreads();
#pragma unroll
    for (int i = 0; i < 4; ++i)
        dst[(size_t)(x0 + ty + 8 * i) * NND + y0 + tx] = __float2half_rn(t[tx][ty + 8 * i]);
}

// ================= kernel 1: H = fp16(silu(X @ W_in + b_in)), 2 cols/thread =================
__global__ __launch_bounds__(256) void k_init(
    const float* __restrict__ X, const float* __restrict__ W_in, const float* __restrict__ b_in)
{
    int idx = blockIdx.x * 256 + threadIdx.x;          // over BATCH * 256 pairs
    int m = idx >> 8;
    int j = (idx & 255) * 2;
    float4 xv = reinterpret_cast<const float4*>(X)[m];
    float a0 = b_in[j] + xv.x * W_in[j] + xv.y * W_in[NND + j]
             + xv.z * W_in[2 * NND + j] + xv.w * W_in[3 * NND + j];
    float a1 = b_in[j + 1] + xv.x * W_in[j + 1] + xv.y * W_in[NND + j + 1]
             + xv.z * W_in[2 * NND + j + 1] + xv.w * W_in[3 * NND + j + 1];
    *reinterpret_cast<__half2*>(&g_H0[(size_t)m * NND + j]) =
        __floats2half2_rn(fsilu(a0), fsilu(a1));
}

// ================= gate GEMM (fp16 mma.sync, 16 warps, 3-stage pipe) =================
// grid (8, 1024): x = 64-col j-block, y = 128-row m-block.
// 512 threads = 16 warps (4M x 4N); warp tile 32(M) x 16(N) per gate. BK=64.
__global__ __launch_bounds__(512, 1) void k_gate_tc(
    int layer, const float* __restrict__ X,
    const float* __restrict__ Wf_, const float* __restrict__ bf_,
    const float* __restrict__ Wu_, const float* __restrict__ bu_,
    const float* __restrict__ Wo_, const float* __restrict__ bo_)
{
    extern __shared__ __half smh[];
    // As: 3 stages x 128 x HST = 3 x 9216 halves
    // Bs: 3 stages x 3 gates x 64 x HST = 3 x 13824 halves
    __half* As = smh;
    __half* Bs = smh + 3 * 9216;
    float* sW  = (float*)(smh + 3 * 9216 + 3 * 13824);   // 768 floats
    float* sBi = sW + 768;                               // 192
    float4* Xs = (float4*)(sBi + 192);                   // 128

    const int tid = threadIdx.x;
    const int lane = tid & 31;
    const int wid = tid >> 5;
    const int wM = wid & 3;                 // 32 rows
    const int wN = wid >> 2;                // 16 cols (per gate)
    const int gid = lane >> 2;
    const int tig = lane & 3;
    const int m0 = blockIdx.y * 128;
    const int j0 = blockIdx.x * 64;

    const __half* __restrict__ Hin = (layer & 1) ? g_H1 : g_H0;
    const __half* __restrict__ UT  = g_UT + (size_t)(layer * 4) * NND * NND;

    const uint32_t aBase = smem_to_u32(As);
    const uint32_t bBase = smem_to_u32(Bs);

    const int lr = lane & 7;
    // A frag (m16 x k16): bit3 -> +8 rows, bit4 -> +8 k-halves (16B)
    uint32_t aoff[2];
#pragma unroll
    for (int mt = 0; mt < 2; ++mt)
        aoff[mt] = (uint32_t)((wM * 32 + mt * 16 + lr + ((lane >> 3) & 1) * 8) * HST * 2
                              + (lane >> 4) * 16);
    // B frag (n16 x k16): bit3 -> +8 k-halves, bit4 -> +8 n-rows
    const uint32_t boff = (uint32_t)((wN * 16 + (lane >> 4) * 8 + lr) * HST * 2
                                     + ((lane >> 3) & 1) * 16);

    for (int o = tid; o < 768; o += 512) {
        int g = o >> 8, rem = o & 255, d = rem >> 6, jl = rem & 63;
        const float* Wsrc = (g == 0) ? Wf_ : ((g == 1) ? Wu_ : Wo_);
        sW[o] = Wsrc[d * NND + j0 + jl];
    }
    if (tid < 192) {
        int g = tid >> 6, jl = tid & 63;
        sBi[tid] = ((g == 0) ? bf_ : ((g == 1) ? bu_ : bo_))[j0 + jl];
    }
    if (tid < 128) Xs[tid] = reinterpret_cast<const float4*>(X)[m0 + tid];

    float acc[3][2][2][4];
#pragma unroll
    for (int g = 0; g < 3; ++g)
#pragma unroll
        for (int mt = 0; mt < 2; ++mt)
#pragma unroll
            for (int nt = 0; nt < 2; ++nt)
#pragma unroll
                for (int q = 0; q < 4; ++q) acc[g][mt][nt][q] = 0.0f;

    auto loadA = [&](int s, int c) {
        const int k0 = c * 64;
#pragma unroll
        for (int i = 0; i < 2; ++i) {
            int e = tid + 512 * i, r = e >> 3, cc = e & 7;
            cp_async16(aBase + (s * 9216 + r * HST) * 2 + cc * 16,
                       Hin + (size_t)(m0 + r) * NND + k0 + cc * 8);
        }
    };
    auto loadB = [&](int s, int c) {
        const int k0 = c * 64;
#pragma unroll
        for (int i = 0; i < 3; ++i) {
            int e = tid + 512 * i, g = e >> 9, rem = e & 511, r = rem >> 3, cc = rem & 7;
            cp_async16(bBase + ((s * 3 + g) * 4608 + r * HST) * 2 + cc * 16,
                       UT + (size_t)g * NND * NND + (size_t)(j0 + r) * NND + k0 + cc * 8);
        }
    };

    loadA(0, 0); loadB(0, 0); cp_commit();
    loadA(1, 1); loadB(1, 1); cp_commit();

#pragma unroll 1
    for (int c = 0; c < NC; ++c) {
        const int s = c % 3;
        if (c + 1 < NC) cp_wait_group<1>(); else cp_wait_group<0>();
        __syncthreads();
        if (c + 2 < NC) {
            const int s2 = (c + 2) % 3;
            loadA(s2, c + 2); loadB(s2, c + 2); cp_commit();
        }
        const uint32_t aS = aBase + (uint32_t)s * 18432;          // 9216 halves * 2B
        const uint32_t bS = bBase + (uint32_t)(s * 3) * 9216;     // 4608 halves * 2B
#pragma unroll
        for (int ks = 0; ks < 4; ++ks) {            // 4 x k16 = 64
            uint32_t a[2][4];
            ldsm4(a[0], aS + aoff[0] + ks * 32);
            ldsm4(a[1], aS + aoff[1] + ks * 32);
#pragma unroll
            for (int g = 0; g < 3; ++g) {
                uint32_t b[4];
                ldsm4(b, bS + (uint32_t)g * 9216 + boff + ks * 32);
                mmaf16(acc[g][0][0], a[0], b[0], b[1]);
                mmaf16(acc[g][1][0], a[1], b[0], b[1]);
                mmaf16(acc[g][0][1], a[0], b[2], b[3]);
                mmaf16(acc[g][1][1], a[1], b[2], b[3]);
            }
        }
    }

    // -------- epilogue: F = sigmoid(.), P = sigmoid(.)*tanh(.), fp16 stores --------
#pragma unroll
    for (int mt = 0; mt < 2; ++mt) {
        int rbase = wM * 32 + mt * 16 + gid;
#pragma unroll
        for (int rr = 0; rr < 2; ++rr) {
            int rloc = rbase + rr * 8;
            int m = m0 + rloc;
            float4 xv = Xs[rloc];
#pragma unroll
            for (int nt = 0; nt < 2; ++nt) {
                int jl = wN * 16 + nt * 8 + 2 * tig;
                float fv[2], pv[2];
#pragma unroll
                for (int cc = 0; cc < 2; ++cc) {
                    int j = jl + cc;
                    float fpre = acc[0][mt][nt][rr * 2 + cc] + sBi[j]
                               + xv.x * sW[j]        + xv.y * sW[64 + j]
                               + xv.z * sW[128 + j]  + xv.w * sW[192 + j];
                    float upre = acc[1][mt][nt][rr * 2 + cc] + sBi[64 + j]
                               + xv.x * sW[256 + j]  + xv.y * sW[320 + j]
                               + xv.z * sW[384 + j]  + xv.w * sW[448 + j];
                    float opre = acc[2][mt][nt][rr * 2 + cc] + sBi[128 + j]
                               + xv.x * sW[512 + j]  + xv.y * sW[576 + j]
                               + xv.z * sW[640 + j]  + xv.w * sW[704 + j];
                    fv[cc] = fsigmoid(fpre);
                    pv[cc] = fsigmoid(upre) * ftanh_(opre);
                }
                size_t ga = (size_t)m * NND + j0 + jl;
                *reinterpret_cast<__half2*>(&g_F[ga]) = __floats2half2_rn(fv[0], fv[1]);
                *reinterpret_cast<__half2*>(&g_P[ga]) = __floats2half2_rn(pv[0], pv[1]);
            }
        }
    }
}

// ================= second GEMM: H_new = F*H + silu(P @ Wo2^T + bo2) =================
// grid (4, 1024): 512 threads = 16 warps (4M x 4N), warp tile 32x32, BK=64.
__global__ __launch_bounds__(512, 1) void k_gemm2_tc(
    int layer, const float* __restrict__ b2)
{
    extern __shared__ __half smh[];
    __half* As = smh;                 // 3 x 9216 halves
    __half* Bs = smh + 3 * 9216;      // 3 x 9216 halves
    float* sBi = (float*)(smh + 6 * 9216);   // 128 floats

    const int tid = threadIdx.x;
    const int lane = tid & 31;
    const int wid = tid >> 5;
    const int wM = wid & 3;
    const int wN = wid >> 2;          // 32 cols
    const int gid = lane >> 2;
    const int tig = lane & 3;
    const int m0 = blockIdx.y * 128;
    const int j0 = blockIdx.x * 128;

    const __half* __restrict__ Hin  = (layer & 1) ? g_H1 : g_H0;
    __half* __restrict__       Hout = (layer & 1) ? g_H0 : g_H1;
    const __half* __restrict__ WT = g_UT + (size_t)(layer * 4 + 3) * NND * NND;

    const uint32_t aBase = smem_to_u32(As);
    const uint32_t bBase = smem_to_u32(Bs);

    const int lr = lane & 7;
    uint32_t aoff[2];
#pragma unroll
    for (int mt = 0; mt < 2; ++mt)
        aoff[mt] = (uint32_t)((wM * 32 + mt * 16 + lr + ((lane >> 3) & 1) * 8) * HST * 2
                              + (lane >> 4) * 16);
    uint32_t boff[2];
#pragma unroll
    for (int p = 0; p < 2; ++p)
        boff[p] = (uint32_t)((wN * 32 + p * 16 + (lane >> 4) * 8 + lr) * HST * 2
                             + ((lane >> 3) & 1) * 16);

    if (tid < 128) sBi[tid] = b2[j0 + tid];

    float acc[2][4][4];
#pragma unroll
    for (int mt = 0; mt < 2; ++mt)
#pragma unroll
        for (int nt = 0; nt < 4; ++nt)
#pragma unroll
            for (int q = 0; q < 4; ++q) acc[mt][nt][q] = 0.0f;

    auto loadA = [&](int s, int c) {
        const int k0 = c * 64;
#pragma unroll
        for (int i = 0; i < 2; ++i) {
            int e = tid + 512 * i, r = e >> 3, cc = e & 7;
            cp_async16(aBase + (s * 9216 + r * HST) * 2 + cc * 16,
                       g_P + (size_t)(m0 + r) * NND + k0 + cc * 8);
        }
    };
    auto loadB = [&](int s, int c) {
        const int k0 = c * 64;
#pragma unroll
        for (int i = 0; i < 2; ++i) {
            int e = tid + 512 * i, r = e >> 3, cc = e & 7;
            cp_async16(bBase + (s * 9216 + r * HST) * 2 + cc * 16,
                       WT + (size_t)(j0 + r) * NND + k0 + cc * 8);
        }
    };

    loadA(0, 0); loadB(0, 0); cp_commit();
    loadA(1, 1); loadB(1, 1); cp_commit();

#pragma unroll 1
    for (int c = 0; c < NC; ++c) {
        const int s = c % 3;
        if (c + 1 < NC) cp_wait_group<1>(); else cp_wait_group<0>();
        __syncthreads();
        if (c + 2 < NC) {
            const int s2 = (c + 2) % 3;
            loadA(s2, c + 2); loadB(s2, c + 2); cp_commit();
        }
        const uint32_t aS = aBase + (uint32_t)s * 18432;
        const uint32_t bS = bBase + (uint32_t)s * 18432;
#pragma unroll
        for (int ks = 0; ks < 4; ++ks) {
            uint32_t a[2][4];
            ldsm4(a[0], aS + aoff[0] + ks * 32);
            ldsm4(a[1], aS + aoff[1] + ks * 32);
#pragma unroll
            for (int p = 0; p < 2; ++p) {
                uint32_t b[4];
                ldsm4(b, bS + boff[p] + ks * 32);
                mmaf16(acc[0][2 * p],     a[0], b[0], b[1]);
                mmaf16(acc[1][2 * p],     a[1], b[0], b[1]);
                mmaf16(acc[0][2 * p + 1], a[0], b[2], b[3]);
                mmaf16(acc[1][2 * p + 1], a[1], b[2], b[3]);
            }
        }
    }

    // -------- epilogue: H_new = F*H + silu(acc + bias), fp16 stores --------
#pragma unroll
    for (int mt = 0; mt < 2; ++mt) {
        int rbase = wM * 32 + mt * 16 + gid;
#pragma unroll
        for (int rr = 0; rr < 2; ++rr) {
            int m = m0 + rbase + rr * 8;
#pragma unroll
            for (int nt = 0; nt < 4; ++nt) {
                int jl = wN * 32 + nt * 8 + 2 * tig;
                size_t ga = (size_t)m * NND + j0 + jl;
                float2 Fv = __half22float2(*reinterpret_cast<const __half2*>(&g_F[ga]));
                float2 Hv = __half22float2(*reinterpret_cast<const __half2*>(&Hin[ga]));
                float h0 = Fv.x * Hv.x + fsilu(acc[mt][nt][rr * 2 + 0] + sBi[jl]);
                float h1 = Fv.y * Hv.y + fsilu(acc[mt][nt][rr * 2 + 1] + sBi[jl + 1]);
                *reinterpret_cast<__half2*>(&Hout[ga]) = __floats2half2_rn(h0, h1);
            }
        }
    }
}

// ================= kernel 4: out = silu(H @ W_out + b_out) =================
__global__ __launch_bounds__(256) void k_out(
    const float* __restrict__ W_out, const float* __restrict__ b_out, float* __restrict__ out)
{
    const __half* __restrict__ H = g_H1;   // after 3 layers: H0->H1->H0->H1
    const int warp = threadIdx.x >> 5;
    const int lane = threadIdx.x & 31;
    const int row = blockIdx.x * 8 + warp;
    const size_t base = (size_t)row * NND;
    float s = 0.0f;
#pragma unroll
    for (int t = 0; t < 8; ++t) {
        int o = lane * 2 + t * 64;
        float2 hv = __half22float2(*reinterpret_cast<const __half2*>(&H[base + o]));
        s += hv.x * W_out[o] + hv.y * W_out[o + 1];
    }
#pragma unroll
    for (int off = 16; off > 0; off >>= 1)
        s += __shfl_down_sync(0xffffffffu, s, off);
    if (lane == 0) out[row] = fsilu(s + b_out[0]);
}

// ================= launch =================
extern "C" void kernel_launch(void* const* d_in, const int* in_sizes, int n_in,
                              void* d_out, int out_size)
{
    const float* X     = (const float*)d_in[0];
    const float* W_in  = (const float*)d_in[1];
    const float* b_in  = (const float*)d_in[2];
    const float* Wf    = (const float*)d_in[3];
    const float* Uf    = (const float*)d_in[4];
    const float* bfp   = (const float*)d_in[5];
    const float* Wu    = (const float*)d_in[6];
    const float* Uu    = (const float*)d_in[7];
    const float* bup   = (const float*)d_in[8];
    const float* Wo1   = (const float*)d_in[9];
    const float* Uo1   = (const float*)d_in[10];
    const float* bo1   = (const float*)d_in[11];
    const float* Wo2   = (const float*)d_in[12];
    const float* bo2   = (const float*)d_in[13];
    const float* W_out = (const float*)d_in[14];
    const float* b_out = (const float*)d_in[15];

    const int SMEM_GATE  = (3 * 9216 + 3 * 13824) * 2 + (768 + 192) * 4 + 128 * 16;  // 144128 B
    const int SMEM_GEMM2 = 6 * 9216 * 2 + 128 * 4;                                   // 111104 B
    cudaFuncSetAttribute(k_gate_tc,  cudaFuncAttributeMaxDynamicSharedMemorySize, SMEM_GATE);
    cudaFuncSetAttribute(k_gemm2_tc, cudaFuncAttributeMaxDynamicSharedMemorySize, SMEM_GEMM2);

    k_transpose<<<dim3(16, 16, NLAYER * 4), 256>>>(Uf, Uu, Uo1, Wo2);
    k_init<<<BATCH, 256>>>(X, W_in, b_in);

    for (int l = 0; l < NLAYER; ++l) {
        const size_t w4 = (size_t)l * 4 * NND;     // [L,4,512] slice
        const size_t b1 = (size_t)l * NND;         // [L,1,512] slice
        k_gate_tc<<<dim3(8, BATCH / 128), 512, SMEM_GATE>>>(
            l, X,
            Wf + w4, bfp + b1,
            Wu + w4, bup + b1,
            Wo1 + w4, bo1 + b1);
        k_gemm2_tc<<<dim3(4, BATCH / 128), 512, SMEM_GEMM2>>>(l, bo2 + b1);
    }

    k_out<<<BATCH / 8, 256>>>(W_out, b_out, (float*)d_out);
}

// round 13
// speedup vs baseline: 3.9251x; 1.0044x over previous
#include <cuda_runtime.h>
#include <cuda_fp16.h>
#include <cstdint>

#define BATCH  131072
#define NND    512
#define NLAYER 3
#define NC     8           // 512 / 64 K-chunks
#define HST    72          // padded smem row stride (halves); 144B, LDSM conflict-free

// ---------------- scratch (device globals; no allocation allowed) ----------------
__device__ __half g_H0[(size_t)BATCH * NND];
__device__ __half g_H1[(size_t)BATCH * NND];
__device__ __half g_F [(size_t)BATCH * NND];
__device__ __half g_P [(size_t)BATCH * NND];
// transposed fp16 weights: [layer][gate: Uf,Uu,Uo1,Wo2][j][k]
__device__ __half g_UT[(size_t)NLAYER * 4 * NND * NND];

// ---------------- PTX helpers ----------------
__device__ __forceinline__ uint32_t smem_to_u32(const void* p) {
    uint32_t a;
    asm("{ .reg .u64 t; cvta.to.shared.u64 t, %1; cvt.u32.u64 %0, t; }" : "=r"(a) : "l"(p));
    return a;
}
__device__ __forceinline__ void cp_async16(uint32_t dst, const void* src) {
    asm volatile("cp.async.cg.shared.global [%0], [%1], 16;"
                 :: "r"(dst), "l"((unsigned long long)__cvta_generic_to_global((void*)src)) : "memory");
}
__device__ __forceinline__ void cp_commit() {
    asm volatile("cp.async.commit_group;" ::: "memory");
}
template <int N> __device__ __forceinline__ void cp_wait_group() {
    asm volatile("cp.async.wait_group %0;" :: "n"(N) : "memory");
}
// D += A(16x16,row) * B(16x8,col); fp16 inputs, fp32 accum
__device__ __forceinline__ void mmaf16(float* c, const uint32_t* a, uint32_t b0, uint32_t b1) {
    asm volatile(
        "mma.sync.aligned.m16n8k16.row.col.f32.f16.f16.f32 "
        "{%0,%1,%2,%3},{%4,%5,%6,%7},{%8,%9},{%0,%1,%2,%3};"
        : "+f"(c[0]), "+f"(c[1]), "+f"(c[2]), "+f"(c[3])
        : "r"(a[0]), "r"(a[1]), "r"(a[2]), "r"(a[3]), "r"(b0), "r"(b1));
}
__device__ __forceinline__ void ldsm4(uint32_t* r, uint32_t addr) {
    asm volatile("ldmatrix.sync.aligned.m8n8.x4.shared.b16 {%0,%1,%2,%3}, [%4];"
        : "=r"(r[0]), "=r"(r[1]), "=r"(r[2]), "=r"(r[3]) : "r"(addr));
}

// ---------------- activations ----------------
__device__ __forceinline__ float fsigmoid(float x) { return __fdividef(1.0f, 1.0f + __expf(-x)); }
__device__ __forceinline__ float ftanh_(float x)   { return 1.0f - __fdividef(2.0f, __expf(2.0f * x) + 1.0f); }
__device__ __forceinline__ float fsilu(float x)    { return x * fsigmoid(x); }

// ================= weight transpose (fp16): g_UT[l][g][j][k] = W[l][g][k][j] =================
__global__ __launch_bounds__(256) void k_transpose(
    const float* __restrict__ Uf, const float* __restrict__ Uu,
    const float* __restrict__ Uo1, const float* __restrict__ Wo2)
{
    __shared__ float t[32][33];
    int mat = blockIdx.z;
    int l = mat >> 2, g = mat & 3;
    const float* srcs[4] = {Uf, Uu, Uo1, Wo2};
    const float* src = srcs[g] + (size_t)l * NND * NND;
    __half* dst = g_UT + (size_t)mat * NND * NND;
    int x0 = blockIdx.x * 32, y0 = blockIdx.y * 32;
    int tx = threadIdx.x & 31, ty = threadIdx.x >> 5;
#pragma unroll
    for (int i = 0; i < 4; ++i)
        t[ty + 8 * i][tx] = src[(size_t)(y0 + ty + 8 * i) * NND + x0 + tx];
    __syncthreads();
#pragma unroll
    for (int i = 0; i < 4; ++i)
        dst[(size_t)(x0 + ty + 8 * i) * NND + y0 + tx] = __float2half_rn(t[tx][ty + 8 * i]);
}

// ================= kernel 1: H = fp16(silu(X @ W_in + b_in)), 2 cols/thread =================
__global__ __launch_bounds__(256) void k_init(
    const float* __restrict__ X, const float* __restrict__ W_in, const float* __restrict__ b_in)
{
    int idx = blockIdx.x * 256 + threadIdx.x;
    int m = idx >> 8;
    int j = (idx & 255) * 2;
    float4 xv = reinterpret_cast<const float4*>(X)[m];
    float a0 = b_in[j] + xv.x * W_in[j] + xv.y * W_in[NND + j]
             + xv.z * W_in[2 * NND + j] + xv.w * W_in[3 * NND + j];
    float a1 = b_in[j + 1] + xv.x * W_in[j + 1] + xv.y * W_in[NND + j + 1]
             + xv.z * W_in[2 * NND + j + 1] + xv.w * W_in[3 * NND + j + 1];
    *reinterpret_cast<__half2*>(&g_H0[(size_t)m * NND + j]) =
        __floats2half2_rn(fsilu(a0), fsilu(a1));
}

// ================= gate GEMM (fp16 mma.sync, 16 warps, 3-stage pipe, frag dbuf) =================
// grid (8, 1024): x = 64-col j-block, y = 128-row m-block.
// 512 threads = 16 warps (4M x 4N); warp tile 32(M) x 16(N) per gate. BK=64.
__global__ __launch_bounds__(512, 1) void k_gate_tc(
    int layer, const float* __restrict__ X,
    const float* __restrict__ Wf_, const float* __restrict__ bf_,
    const float* __restrict__ Wu_, const float* __restrict__ bu_,
    const float* __restrict__ Wo_, const float* __restrict__ bo_)
{
    extern __shared__ __half smh[];
    __half* As = smh;                                    // 3 x 9216 halves
    __half* Bs = smh + 3 * 9216;                         // 3 x 13824 halves
    float* sW  = (float*)(smh + 3 * 9216 + 3 * 13824);   // 768 floats
    float* sBi = sW + 768;                               // 192
    float4* Xs = (float4*)(sBi + 192);                   // 128

    const int tid = threadIdx.x;
    const int lane = tid & 31;
    const int wid = tid >> 5;
    const int wM = wid & 3;
    const int wN = wid >> 2;
    const int gid = lane >> 2;
    const int tig = lane & 3;
    const int m0 = blockIdx.y * 128;
    const int j0 = blockIdx.x * 64;

    const __half* __restrict__ Hin = (layer & 1) ? g_H1 : g_H0;
    const __half* __restrict__ UT  = g_UT + (size_t)(layer * 4) * NND * NND;

    const uint32_t aBase = smem_to_u32(As);
    const uint32_t bBase = smem_to_u32(Bs);

    const int lr = lane & 7;
    uint32_t aoff[2];
#pragma unroll
    for (int mt = 0; mt < 2; ++mt)
        aoff[mt] = (uint32_t)((wM * 32 + mt * 16 + lr + ((lane >> 3) & 1) * 8) * HST * 2
                              + (lane >> 4) * 16);
    const uint32_t boff = (uint32_t)((wN * 16 + (lane >> 4) * 8 + lr) * HST * 2
                                     + ((lane >> 3) & 1) * 16);

    for (int o = tid; o < 768; o += 512) {
        int g = o >> 8, rem = o & 255, d = rem >> 6, jl = rem & 63;
        const float* Wsrc = (g == 0) ? Wf_ : ((g == 1) ? Wu_ : Wo_);
        sW[o] = Wsrc[d * NND + j0 + jl];
    }
    if (tid < 192) {
        int g = tid >> 6, jl = tid & 63;
        sBi[tid] = ((g == 0) ? bf_ : ((g == 1) ? bu_ : bo_))[j0 + jl];
    }
    if (tid < 128) Xs[tid] = reinterpret_cast<const float4*>(X)[m0 + tid];

    float acc[3][2][2][4];
#pragma unroll
    for (int g = 0; g < 3; ++g)
#pragma unroll
        for (int mt = 0; mt < 2; ++mt)
#pragma unroll
            for (int nt = 0; nt < 2; ++nt)
#pragma unroll
                for (int q = 0; q < 4; ++q) acc[g][mt][nt][q] = 0.0f;

    auto loadA = [&](int s, int c) {
        const int k0 = c * 64;
#pragma unroll
        for (int i = 0; i < 2; ++i) {
            int e = tid + 512 * i, r = e >> 3, cc = e & 7;
            cp_async16(aBase + (s * 9216 + r * HST) * 2 + cc * 16,
                       Hin + (size_t)(m0 + r) * NND + k0 + cc * 8);
        }
    };
    auto loadB = [&](int s, int c) {
        const int k0 = c * 64;
#pragma unroll
        for (int i = 0; i < 3; ++i) {
            int e = tid + 512 * i, g = e >> 9, rem = e & 511, r = rem >> 3, cc = rem & 7;
            cp_async16(bBase + ((s * 3 + g) * 4608 + r * HST) * 2 + cc * 16,
                       UT + (size_t)g * NND * NND + (size_t)(j0 + r) * NND + k0 + cc * 8);
        }
    };

    loadA(0, 0); loadB(0, 0); cp_commit();
    loadA(1, 1); loadB(1, 1); cp_commit();

#pragma unroll 1
    for (int c = 0; c < NC; ++c) {
        const int s = c % 3;
        if (c + 1 < NC) cp_wait_group<1>(); else cp_wait_group<0>();
        __syncthreads();
        if (c + 2 < NC) {
            const int s2 = (c + 2) % 3;
            loadA(s2, c + 2); loadB(s2, c + 2); cp_commit();
        }
        const uint32_t aS = aBase + (uint32_t)s * 18432;
        const uint32_t bS = bBase + (uint32_t)(s * 3) * 9216;

        // fragment double buffer: prefetch ks+1 while issuing ks MMAs
        uint32_t a[2][2][4], b[2][3][4];
        ldsm4(a[0][0], aS + aoff[0]);
        ldsm4(a[0][1], aS + aoff[1]);
#pragma unroll
        for (int g = 0; g < 3; ++g)
            ldsm4(b[0][g], bS + (uint32_t)g * 9216 + boff);
#pragma unroll
        for (int ks = 0; ks < 4; ++ks) {
            const int cur = ks & 1, nxt = cur ^ 1;
            if (ks < 3) {
                ldsm4(a[nxt][0], aS + aoff[0] + (ks + 1) * 32);
                ldsm4(a[nxt][1], aS + aoff[1] + (ks + 1) * 32);
#pragma unroll
                for (int g = 0; g < 3; ++g)
                    ldsm4(b[nxt][g], bS + (uint32_t)g * 9216 + boff + (ks + 1) * 32);
            }
#pragma unroll
            for (int g = 0; g < 3; ++g) {
                mmaf16(acc[g][0][0], a[cur][0], b[cur][g][0], b[cur][g][1]);
                mmaf16(acc[g][1][0], a[cur][1], b[cur][g][0], b[cur][g][1]);
                mmaf16(acc[g][0][1], a[cur][0], b[cur][g][2], b[cur][g][3]);
                mmaf16(acc[g][1][1], a[cur][1], b[cur][g][2], b[cur][g][3]);
            }
        }
    }

    // -------- epilogue: F = sigmoid(.), P = sigmoid(.)*tanh(.), fp16 stores --------
#pragma unroll
    for (int mt = 0; mt < 2; ++mt) {
        int rbase = wM * 32 + mt * 16 + gid;
#pragma unroll
        for (int rr = 0; rr < 2; ++rr) {
            int rloc = rbase + rr * 8;
            int m = m0 + rloc;
            float4 xv = Xs[rloc];
#pragma unroll
            for (int nt = 0; nt < 2; ++nt) {
                int jl = wN * 16 + nt * 8 + 2 * tig;
                float fv[2], pv[2];
#pragma unroll
                for (int cc = 0; cc < 2; ++cc) {
                    int j = jl + cc;
                    float fpre = acc[0][mt][nt][rr * 2 + cc] + sBi[j]
                               + xv.x * sW[j]        + xv.y * sW[64 + j]
                               + xv.z * sW[128 + j]  + xv.w * sW[192 + j];
                    float upre = acc[1][mt][nt][rr * 2 + cc] + sBi[64 + j]
                               + xv.x * sW[256 + j]  + xv.y * sW[320 + j]
                               + xv.z * sW[384 + j]  + xv.w * sW[448 + j];
                    float opre = acc[2][mt][nt][rr * 2 + cc] + sBi[128 + j]
                               + xv.x * sW[512 + j]  + xv.y * sW[576 + j]
                               + xv.z * sW[640 + j]  + xv.w * sW[704 + j];
                    fv[cc] = fsigmoid(fpre);
                    pv[cc] = fsigmoid(upre) * ftanh_(opre);
                }
                size_t ga = (size_t)m * NND + j0 + jl;
                *reinterpret_cast<__half2*>(&g_F[ga]) = __floats2half2_rn(fv[0], fv[1]);
                *reinterpret_cast<__half2*>(&g_P[ga]) = __floats2half2_rn(pv[0], pv[1]);
            }
        }
    }
}

// ================= second GEMM: H_new = F*H + silu(P @ Wo2^T + bo2) =================
// grid (4, 1024): 512 threads = 16 warps (4M x 4N), warp tile 32x32, BK=64, frag dbuf.
__global__ __launch_bounds__(512, 1) void k_gemm2_tc(
    int layer, const float* __restrict__ b2)
{
    extern __shared__ __half smh[];
    __half* As = smh;                        // 3 x 9216 halves
    __half* Bs = smh + 3 * 9216;             // 3 x 9216 halves
    float* sBi = (float*)(smh + 6 * 9216);   // 128 floats

    const int tid = threadIdx.x;
    const int lane = tid & 31;
    const int wid = tid >> 5;
    const int wM = wid & 3;
    const int wN = wid >> 2;
    const int gid = lane >> 2;
    const int tig = lane & 3;
    const int m0 = blockIdx.y * 128;
    const int j0 = blockIdx.x * 128;

    const __half* __restrict__ Hin  = (layer & 1) ? g_H1 : g_H0;
    __half* __restrict__       Hout = (layer & 1) ? g_H0 : g_H1;
    const __half* __restrict__ WT = g_UT + (size_t)(layer * 4 + 3) * NND * NND;

    const uint32_t aBase = smem_to_u32(As);
    const uint32_t bBase = smem_to_u32(Bs);

    const int lr = lane & 7;
    uint32_t aoff[2];
#pragma unroll
    for (int mt = 0; mt < 2; ++mt)
        aoff[mt] = (uint32_t)((wM * 32 + mt * 16 + lr + ((lane >> 3) & 1) * 8) * HST * 2
                              + (lane >> 4) * 16);
    uint32_t boff[2];
#pragma unroll
    for (int p = 0; p < 2; ++p)
        boff[p] = (uint32_t)((wN * 32 + p * 16 + (lane >> 4) * 8 + lr) * HST * 2
                             + ((lane >> 3) & 1) * 16);

    if (tid < 128) sBi[tid] = b2[j0 + tid];

    float acc[2][4][4];
#pragma unroll
    for (int mt = 0; mt < 2; ++mt)
#pragma unroll
        for (int nt = 0; nt < 4; ++nt)
#pragma unroll
            for (int q = 0; q < 4; ++q) acc[mt][nt][q] = 0.0f;

    auto loadA = [&](int s, int c) {
        const int k0 = c * 64;
#pragma unroll
        for (int i = 0; i < 2; ++i) {
            int e = tid + 512 * i, r = e >> 3, cc = e & 7;
            cp_async16(aBase + (s * 9216 + r * HST) * 2 + cc * 16,
                       g_P + (size_t)(m0 + r) * NND + k0 + cc * 8);
        }
    };
    auto loadB = [&](int s, int c) {
        const int k0 = c * 64;
#pragma unroll
        for (int i = 0; i < 2; ++i) {
            int e = tid + 512 * i, r = e >> 3, cc = e & 7;
            cp_async16(bBase + (s * 9216 + r * HST) * 2 + cc * 16,
                       WT + (size_t)(j0 + r) * NND + k0 + cc * 8);
        }
    };

    loadA(0, 0); loadB(0, 0); cp_commit();
    loadA(1, 1); loadB(1, 1); cp_commit();

#pragma unroll 1
    for (int c = 0; c < NC; ++c) {
        const int s = c % 3;
        if (c + 1 < NC) cp_wait_group<1>(); else cp_wait_group<0>();
        __syncthreads();
        if (c + 2 < NC) {
            const int s2 = (c + 2) % 3;
            loadA(s2, c + 2); loadB(s2, c + 2); cp_commit();
        }
        const uint32_t aS = aBase + (uint32_t)s * 18432;
        const uint32_t bS = bBase + (uint32_t)s * 18432;

        uint32_t a[2][2][4], b[2][2][4];
        ldsm4(a[0][0], aS + aoff[0]);
        ldsm4(a[0][1], aS + aoff[1]);
        ldsm4(b[0][0], bS + boff[0]);
        ldsm4(b[0][1], bS + boff[1]);
#pragma unroll
        for (int ks = 0; ks < 4; ++ks) {
            const int cur = ks & 1, nxt = cur ^ 1;
            if (ks < 3) {
                ldsm4(a[nxt][0], aS + aoff[0] + (ks + 1) * 32);
                ldsm4(a[nxt][1], aS + aoff[1] + (ks + 1) * 32);
                ldsm4(b[nxt][0], bS + boff[0] + (ks + 1) * 32);
                ldsm4(b[nxt][1], bS + boff[1] + (ks + 1) * 32);
            }
#pragma unroll
            for (int p = 0; p < 2; ++p) {
                mmaf16(acc[0][2 * p],     a[cur][0], b[cur][p][0], b[cur][p][1]);
                mmaf16(acc[1][2 * p],     a[cur][1], b[cur][p][0], b[cur][p][1]);
                mmaf16(acc[0][2 * p + 1], a[cur][0], b[cur][p][2], b[cur][p][3]);
                mmaf16(acc[1][2 * p + 1], a[cur][1], b[cur][p][2], b[cur][p][3]);
            }
        }
    }

    // -------- epilogue: H_new = F*H + silu(acc + bias), fp16 stores --------
#pragma unroll
    for (int mt = 0; mt < 2; ++mt) {
        int rbase = wM * 32 + mt * 16 + gid;
#pragma unroll
        for (int rr = 0; rr < 2; ++rr) {
            int m = m0 + rbase + rr * 8;
#pragma unroll
            for (int nt = 0; nt < 4; ++nt) {
                int jl = wN * 32 + nt * 8 + 2 * tig;
                size_t ga = (size_t)m * NND + j0 + jl;
                float2 Fv = __half22float2(*reinterpret_cast<const __half2*>(&g_F[ga]));
                float2 Hv = __half22float2(*reinterpret_cast<const __half2*>(&Hin[ga]));
                float h0 = Fv.x * Hv.x + fsilu(acc[mt][nt][rr * 2 + 0] + sBi[jl]);
                float h1 = Fv.y * Hv.y + fsilu(acc[mt][nt][rr * 2 + 1] + sBi[jl + 1]);
                *reinterpret_cast<__half2*>(&Hout[ga]) = __floats2half2_rn(h0, h1);
            }
        }
    }
}

// ================= kernel 4: out = silu(H @ W_out + b_out) =================
__global__ __launch_bounds__(256) void k_out(
    const float* __restrict__ W_out, const float* __restrict__ b_out, float* __restrict__ out)
{
    const __half* __restrict__ H = g_H1;   // after 3 layers: H0->H1->H0->H1
    const int warp = threadIdx.x >> 5;
    const int lane = threadIdx.x & 31;
    const int row = blockIdx.x * 8 + warp;
    const size_t base = (size_t)row * NND;
    float s = 0.0f;
#pragma unroll
    for (int t = 0; t < 8; ++t) {
        int o = lane * 2 + t * 64;
        float2 hv = __half22float2(*reinterpret_cast<const __half2*>(&H[base + o]));
        s += hv.x * W_out[o] + hv.y * W_out[o + 1];
    }
#pragma unroll
    for (int off = 16; off > 0; off >>= 1)
        s += __shfl_down_sync(0xffffffffu, s, off);
    if (lane == 0) out[row] = fsilu(s + b_out[0]);
}

// ================= launch =================
extern "C" void kernel_launch(void* const* d_in, const int* in_sizes, int n_in,
                              void* d_out, int out_size)
{
    const float* X     = (const float*)d_in[0];
    const float* W_in  = (const float*)d_in[1];
    const float* b_in  = (const float*)d_in[2];
    const float* Wf    = (const float*)d_in[3];
    const float* Uf    = (const float*)d_in[4];
    const float* bfp   = (const float*)d_in[5];
    const float* Wu    = (const float*)d_in[6];
    const float* Uu    = (const float*)d_in[7];
    const float* bup   = (const float*)d_in[8];
    const float* Wo1   = (const float*)d_in[9];
    const float* Uo1   = (const float*)d_in[10];
    const float* bo1   = (const float*)d_in[11];
    const float* Wo2   = (const float*)d_in[12];
    const float* bo2   = (const float*)d_in[13];
    const float* W_out = (const float*)d_in[14];
    const float* b_out = (const float*)d_in[15];

    const int SMEM_GATE  = (3 * 9216 + 3 * 13824) * 2 + (768 + 192) * 4 + 128 * 16;  // 144128 B
    const int SMEM_GEMM2 = 6 * 9216 * 2 + 128 * 4;                                   // 111104 B
    cudaFuncSetAttribute(k_gate_tc,  cudaFuncAttributeMaxDynamicSharedMemorySize, SMEM_GATE);
    cudaFuncSetAttribute(k_gemm2_tc, cudaFuncAttributeMaxDynamicSharedMemorySize, SMEM_GEMM2);

    k_transpose<<<dim3(16, 16, NLAYER * 4), 256>>>(Uf, Uu, Uo1, Wo2);
    k_init<<<BATCH, 256>>>(X, W_in, b_in);

    for (int l = 0; l < NLAYER; ++l) {
        const size_t w4 = (size_t)l * 4 * NND;     // [L,4,512] slice
        const size_t b1 = (size_t)l * NND;         // [L,1,512] slice
        k_gate_tc<<<dim3(8, BATCH / 128), 512, SMEM_GATE>>>(
            l, X,
            Wf + w4, bfp + b1,
            Wu + w4, bup + b1,
            Wo1 + w4, bo1 + b1);
        k_gemm2_tc<<<dim3(4, BATCH / 128), 512, SMEM_GEMM2>>>(l, bo2 + b1);
    }

    k_out<<<BATCH / 8, 256>>>(W_out, b_out, (float*)d_out);
}

// round 15
// speedup vs baseline: 3.9480x; 1.0058x over previous
#include <cuda_runtime.h>
#include <cuda_fp16.h>
#include <cstdint>

#define BATCH  131072
#define NND    512
#define NLAYER 3
#define NC     8           // 512 / 64 K-chunks
#define HST    72          // padded smem row stride (halves); 144B, LDSM conflict-free

// ---------------- scratch (device globals; no allocation allowed) ----------------
__device__ __half g_H0[(size_t)BATCH * NND];
__device__ __half g_H1[(size_t)BATCH * NND];
__device__ __half g_F [(size_t)BATCH * NND];
__device__ __half g_P [(size_t)BATCH * NND];
// transposed fp16 weights: [layer][gate: Uf,Uu,Uo1,Wo2][j][k]
__device__ __half g_UT[(size_t)NLAYER * 4 * NND * NND];

// ---------------- PTX helpers ----------------
__device__ __forceinline__ uint32_t smem_to_u32(const void* p) {
    uint32_t a;
    asm("{ .reg .u64 t; cvta.to.shared.u64 t, %1; cvt.u32.u64 %0, t; }" : "=r"(a) : "l"(p));
    return a;
}
__device__ __forceinline__ void cp_async16(uint32_t dst, const void* src) {
    asm volatile("cp.async.cg.shared.global [%0], [%1], 16;"
                 :: "r"(dst), "l"((unsigned long long)__cvta_generic_to_global((void*)src)) : "memory");
}
__device__ __forceinline__ void cp_commit() {
    asm volatile("cp.async.commit_group;" ::: "memory");
}
template <int N> __device__ __forceinline__ void cp_wait_group() {
    asm volatile("cp.async.wait_group %0;" :: "n"(N) : "memory");
}
// D += A(16x16,row) * B(16x8,col); fp16 inputs, fp32 accum
__device__ __forceinline__ void mmaf16(float* c, const uint32_t* a, uint32_t b0, uint32_t b1) {
    asm volatile(
        "mma.sync.aligned.m16n8k16.row.col.f32.f16.f16.f32 "
        "{%0,%1,%2,%3},{%4,%5,%6,%7},{%8,%9},{%0,%1,%2,%3};"
        : "+f"(c[0]), "+f"(c[1]), "+f"(c[2]), "+f"(c[3])
        : "r"(a[0]), "r"(a[1]), "r"(a[2]), "r"(a[3]), "r"(b0), "r"(b1));
}
__device__ __forceinline__ void ldsm4(uint32_t* r, uint32_t addr) {
    asm volatile("ldmatrix.sync.aligned.m8n8.x4.shared.b16 {%0,%1,%2,%3}, [%4];"
        : "=r"(r[0]), "=r"(r[1]), "=r"(r[2]), "=r"(r[3]) : "r"(addr));
}

// ---------------- activations ----------------
__device__ __forceinline__ float fsigmoid(float x) { return __fdividef(1.0f, 1.0f + __expf(-x)); }
__device__ __forceinline__ float ftanh_(float x)   { return 1.0f - __fdividef(2.0f, __expf(2.0f * x) + 1.0f); }
__device__ __forceinline__ float fsilu(float x)    { return x * fsigmoid(x); }

// ================= weight transpose (fp16): g_UT[l][g][j][k] = W[l][g][k][j] =================
__global__ __launch_bounds__(256) void k_transpose(
    const float* __restrict__ Uf, const float* __restrict__ Uu,
    const float* __restrict__ Uo1, const float* __restrict__ Wo2)
{
    __shared__ float t[32][33];
    int mat = blockIdx.z;
    int l = mat >> 2, g = mat & 3;
    const float* srcs[4] = {Uf, Uu, Uo1, Wo2};
    const float* src = srcs[g] + (size_t)l * NND * NND;
    __half* dst = g_UT + (size_t)mat * NND * NND;
    int x0 = blockIdx.x * 32, y0 = blockIdx.y * 32;
    int tx = threadIdx.x & 31, ty = threadIdx.x >> 5;
#pragma unroll
    for (int i = 0; i < 4; ++i)
        t[ty + 8 * i][tx] = src[(size_t)(y0 + ty + 8 * i) * NND + x0 + tx];
    __syncthreads();
#pragma unroll
    for (int i = 0; i < 4; ++i)
        dst[(size_t)(x0 + ty + 8 * i) * NND + y0 + tx] = __float2half_rn(t[tx][ty + 8 * i]);
}

// ================= kernel 1: H = fp16(silu(X @ W_in + b_in)), 2 cols/thread =================
__global__ __launch_bounds__(256) void k_init(
    const float* __restrict__ X, const float* __restrict__ W_in, const float* __restrict__ b_in)
{
    int idx = blockIdx.x * 256 + threadIdx.x;
    int m = idx >> 8;
    int j = (idx & 255) * 2;
    float4 xv = reinterpret_cast<const float4*>(X)[m];
    float a0 = b_in[j] + xv.x * W_in[j] + xv.y * W_in[NND + j]
             + xv.z * W_in[2 * NND + j] + xv.w * W_in[3 * NND + j];
    float a1 = b_in[j + 1] + xv.x * W_in[j + 1] + xv.y * W_in[NND + j + 1]
             + xv.z * W_in[2 * NND + j + 1] + xv.w * W_in[3 * NND + j + 1];
    *reinterpret_cast<__half2*>(&g_H0[(size_t)m * NND + j]) =
        __floats2half2_rn(fsilu(a0), fsilu(a1));
}

// ================= gate GEMM (fp16 mma.sync, 16 warps, 3-stage, 2 CTAs/SM) =================
// grid (16, 1024): x = 32-col j-block, y = 128-row m-block.
// 512 threads = 16 warps (8M x 2N); warp tile 16(M) x 16(N) per gate. BK=64.
__global__ __launch_bounds__(512, 2) void k_gate_tc(
    int layer, const float* __restrict__ X,
    const float* __restrict__ Wf_, const float* __restrict__ bf_,
    const float* __restrict__ Wu_, const float* __restrict__ bu_,
    const float* __restrict__ Wo_, const float* __restrict__ bo_)
{
    extern __shared__ __half smh[];
    __half* As = smh;                                    // 3 x 9216 halves (128 x HST)
    __half* Bs = smh + 3 * 9216;                         // 3 x 3 x 2304 halves (32 x HST per gate)
    float* sW  = (float*)(smh + 3 * 9216 + 9 * 2304);    // 384 floats: [gate][d][32]
    float* sBi = sW + 384;                               // 96
    float4* Xs = (float4*)(sBi + 96);                    // 128

    const int tid = threadIdx.x;
    const int lane = tid & 31;
    const int wid = tid >> 5;
    const int wM = wid & 7;                 // 8 M-warps x 16 rows
    const int wN = wid >> 3;                // 2 N-warps x 16 cols (per gate)
    const int gid = lane >> 2;
    const int tig = lane & 3;
    const int m0 = blockIdx.y * 128;
    const int j0 = blockIdx.x * 32;

    const __half* __restrict__ Hin = (layer & 1) ? g_H1 : g_H0;
    const __half* __restrict__ UT  = g_UT + (size_t)(layer * 4) * NND * NND;

    const uint32_t aBase = smem_to_u32(As);
    const uint32_t bBase = smem_to_u32(Bs);

    const int lr = lane & 7;
    // A frag (m16 x k16): one ldsm4 per ks
    const uint32_t aoff = (uint32_t)((wM * 16 + lr + ((lane >> 3) & 1) * 8) * HST * 2
                                     + (lane >> 4) * 16);
    // B frag (n16 x k16)
    const uint32_t boff = (uint32_t)((wN * 16 + (lane >> 4) * 8 + lr) * HST * 2
                                     + ((lane >> 3) & 1) * 16);

    if (tid < 384) {
        int g = tid >> 7, rem = tid & 127, d = rem >> 5, jl = rem & 31;
        const float* Wsrc = (g == 0) ? Wf_ : ((g == 1) ? Wu_ : Wo_);
        sW[tid] = Wsrc[d * NND + j0 + jl];
    }
    if (tid < 96) {
        int g = tid >> 5, jl = tid & 31;
        sBi[tid] = ((g == 0) ? bf_ : ((g == 1) ? bu_ : bo_))[j0 + jl];
    }
    if (tid < 128) Xs[tid] = reinterpret_cast<const float4*>(X)[m0 + tid];

    float acc[3][2][4];                    // [gate][nt][quad]
#pragma unroll
    for (int g = 0; g < 3; ++g)
#pragma unroll
        for (int nt = 0; nt < 2; ++nt)
#pragma unroll
            for (int q = 0; q < 4; ++q) acc[g][nt][q] = 0.0f;

    auto loadA = [&](int s, int c) {
        const int k0 = c * 64;
#pragma unroll
        for (int i = 0; i < 2; ++i) {
            int e = tid + 512 * i, r = e >> 3, cc = e & 7;
            cp_async16(aBase + (s * 9216 + r * HST) * 2 + cc * 16,
                       Hin + (size_t)(m0 + r) * NND + k0 + cc * 8);
        }
    };
    auto loadB = [&](int s, int c) {
        const int k0 = c * 64;
#pragma unroll
        for (int i = 0; i < 2; ++i) {
            int e = tid + 512 * i;
            if (e < 768) {
                int g = e >> 8, rem = e & 255, r = rem >> 3, cc = rem & 7;
                cp_async16(bBase + ((s * 3 + g) * 2304 + r * HST) * 2 + cc * 16,
                           UT + (size_t)g * NND * NND + (size_t)(j0 + r) * NND + k0 + cc * 8);
            }
        }
    };

    loadA(0, 0); loadB(0, 0); cp_commit();
    loadA(1, 1); loadB(1, 1); cp_commit();

#pragma unroll 1
    for (int c = 0; c < NC; ++c) {
        const int s = c % 3;
        if (c + 1 < NC) cp_wait_group<1>(); else cp_wait_group<0>();
        __syncthreads();
        if (c + 2 < NC) {
            const int s2 = (c + 2) % 3;
            loadA(s2, c + 2); loadB(s2, c + 2); cp_commit();
        }
        const uint32_t aS = aBase + (uint32_t)s * 18432;
#pragma unroll
        for (int ks = 0; ks < 4; ++ks) {
            uint32_t a[4];
            ldsm4(a, aS + aoff + ks * 32);
#pragma unroll
            for (int g = 0; g < 3; ++g) {
                uint32_t b[4];
                ldsm4(b, bBase + (uint32_t)((s * 3 + g) * 4608) + boff + ks * 32);
                mmaf16(acc[g][0], a, b[0], b[1]);
                mmaf16(acc[g][1], a, b[2], b[3]);
            }
        }
    }

    // -------- epilogue: F = sigmoid(.), P = sigmoid(.)*tanh(.), fp16 stores --------
#pragma unroll
    for (int rr = 0; rr < 2; ++rr) {
        int rloc = wM * 16 + gid + rr * 8;
        int m = m0 + rloc;
        float4 xv = Xs[rloc];
#pragma unroll
        for (int nt = 0; nt < 2; ++nt) {
            int jl = wN * 16 + nt * 8 + 2 * tig;
            float fv[2], pv[2];
#pragma unroll
            for (int cc = 0; cc < 2; ++cc) {
                int j = jl + cc;
                float fpre = acc[0][nt][rr * 2 + cc] + sBi[j]
                           + xv.x * sW[j]       + xv.y * sW[32 + j]
                           + xv.z * sW[64 + j]  + xv.w * sW[96 + j];
                float upre = acc[1][nt][rr * 2 + cc] + sBi[32 + j]
                           + xv.x * sW[128 + j] + xv.y * sW[160 + j]
                           + xv.z * sW[192 + j] + xv.w * sW[224 + j];
                float opre = acc[2][nt][rr * 2 + cc] + sBi[64 + j]
                           + xv.x * sW[256 + j] + xv.y * sW[288 + j]
                           + xv.z * sW[320 + j] + xv.w * sW[352 + j];
                fv[cc] = fsigmoid(fpre);
                pv[cc] = fsigmoid(upre) * ftanh_(opre);
            }
            size_t ga = (size_t)m * NND + j0 + jl;
            *reinterpret_cast<__half2*>(&g_F[ga]) = __floats2half2_rn(fv[0], fv[1]);
            *reinterpret_cast<__half2*>(&g_P[ga]) = __floats2half2_rn(pv[0], pv[1]);
        }
    }
}

// ================= second GEMM: H_new = F*H + silu(P @ Wo2^T + bo2) =================
// grid (8, 1024): 512 threads = 16 warps (4M x 4N), warp tile 32x16, BK=64, 2 CTAs/SM.
__global__ __launch_bounds__(512, 2) void k_gemm2_tc(
    int layer, const float* __restrict__ b2)
{
    extern __shared__ __half smh[];
    __half* As = smh;                        // 3 x 9216 halves (128 x HST)
    __half* Bs = smh + 3 * 9216;             // 3 x 4608 halves (64 x HST)
    float* sBi = (float*)(smh + 3 * 9216 + 3 * 4608);   // 64 floats

    const int tid = threadIdx.x;
    const int lane = tid & 31;
    const int wid = tid >> 5;
    const int wM = wid & 3;                  // 4 M-warps x 32 rows
    const int wN = wid >> 2;                 // 4 N-warps x 16 cols
    const int gid = lane >> 2;
    const int tig = lane & 3;
    const int m0 = blockIdx.y * 128;
    const int j0 = blockIdx.x * 64;

    const __half* __restrict__ Hin  = (layer & 1) ? g_H1 : g_H0;
    __half* __restrict__       Hout = (layer & 1) ? g_H0 : g_H1;
    const __half* __restrict__ WT = g_UT + (size_t)(layer * 4 + 3) * NND * NND;

    const uint32_t aBase = smem_to_u32(As);
    const uint32_t bBase = smem_to_u32(Bs);

    const int lr = lane & 7;
    uint32_t aoff[2];
#pragma unroll
    for (int mt = 0; mt < 2; ++mt)
        aoff[mt] = (uint32_t)((wM * 32 + mt * 16 + lr + ((lane >> 3) & 1) * 8) * HST * 2
                              + (lane >> 4) * 16);
    const uint32_t boff = (uint32_t)((wN * 16 + (lane >> 4) * 8 + lr) * HST * 2
                                     + ((lane >> 3) & 1) * 16);

    if (tid < 64) sBi[tid] = b2[j0 + tid];

    float acc[2][2][4];                      // [mt][nt][quad]
#pragma unroll
    for (int mt = 0; mt < 2; ++mt)
#pragma unroll
        for (int nt = 0; nt < 2; ++nt)
#pragma unroll
            for (int q = 0; q < 4; ++q) acc[mt][nt][q] = 0.0f;

    auto loadA = [&](int s, int c) {
        const int k0 = c * 64;
#pragma unroll
        for (int i = 0; i < 2; ++i) {
            int e = tid + 512 * i, r = e >> 3, cc = e & 7;
            cp_async16(aBase + (s * 9216 + r * HST) * 2 + cc * 16,
                       g_P + (size_t)(m0 + r) * NND + k0 + cc * 8);
        }
    };
    auto loadB = [&](int s, int c) {
        const int k0 = c * 64;
        int r = tid >> 3, cc = tid & 7;
        if (tid < 512)
            cp_async16(bBase + (s * 4608 + r * HST) * 2 + cc * 16,
                       WT + (size_t)(j0 + r) * NND + k0 + cc * 8);
    };

    loadA(0, 0); loadB(0, 0); cp_commit();
    loadA(1, 1); loadB(1, 1); cp_commit();

#pragma unroll 1
    for (int c = 0; c < NC; ++c) {
        const int s = c % 3;
        if (c + 1 < NC) cp_wait_group<1>(); else cp_wait_group<0>();
        __syncthreads();
        if (c + 2 < NC) {
            const int s2 = (c + 2) % 3;
            loadA(s2, c + 2); loadB(s2, c + 2); cp_commit();
        }
        const uint32_t aS = aBase + (uint32_t)s * 18432;
        const uint32_t bS = bBase + (uint32_t)s * 9216;
#pragma unroll
        for (int ks = 0; ks < 4; ++ks) {
            uint32_t a[2][4], b[4];
            ldsm4(a[0], aS + aoff[0] + ks * 32);
            ldsm4(a[1], aS + aoff[1] + ks * 32);
            ldsm4(b, bS + boff + ks * 32);
            mmaf16(acc[0][0], a[0], b[0], b[1]);
            mmaf16(acc[1][0], a[1], b[0], b[1]);
            mmaf16(acc[0][1], a[0], b[2], b[3]);
            mmaf16(acc[1][1], a[1], b[2], b[3]);
        }
    }

    // -------- epilogue: H_new = F*H + silu(acc + bias), fp16 stores --------
#pragma unroll
    for (int mt = 0; mt < 2; ++mt) {
#pragma unroll
        for (int rr = 0; rr < 2; ++rr) {
            int m = m0 + wM * 32 + mt * 16 + gid + rr * 8;
#pragma unroll
            for (int nt = 0; nt < 2; ++nt) {
                int jl = wN * 16 + nt * 8 + 2 * tig;
                size_t ga = (size_t)m * NND + j0 + jl;
                float2 Fv = __half22float2(*reinterpret_cast<const __half2*>(&g_F[ga]));
                float2 Hv = __half22float2(*reinterpret_cast<const __half2*>(&Hin[ga]));
                float h0 = Fv.x * Hv.x + fsilu(acc[mt][nt][rr * 2 + 0] + sBi[jl]);
                float h1 = Fv.y * Hv.y + fsilu(acc[mt][nt][rr * 2 + 1] + sBi[jl + 1]);
                *reinterpret_cast<__half2*>(&Hout[ga]) = __floats2half2_rn(h0, h1);
            }
        }
    }
}

// ================= kernel 4: out = silu(H @ W_out + b_out) =================
__global__ __launch_bounds__(256) void k_out(
    const float* __restrict__ W_out, const float* __restrict__ b_out, float* __restrict__ out)
{
    const __half* __restrict__ H = g_H1;   // after 3 layers: H0->H1->H0->H1
    const int warp = threadIdx.x >> 5;
    const int lane = threadIdx.x & 31;
    const int row = blockIdx.x * 8 + warp;
    const size_t base = (size_t)row * NND;
    float s = 0.0f;
#pragma unroll
    for (int t = 0; t < 8; ++t) {
        int o = lane * 2 + t * 64;
        float2 hv = __half22float2(*reinterpret_cast<const __half2*>(&H[base + o]));
        s += hv.x * W_out[o] + hv.y * W_out[o + 1];
    }
#pragma unroll
    for (int off = 16; off > 0; off >>= 1)
        s += __shfl_down_sync(0xffffffffu, s, off);
    if (lane == 0) out[row] = fsilu(s + b_out[0]);
}

// ================= launch =================
extern "C" void kernel_launch(void* const* d_in, const int* in_sizes, int n_in,
                              void* d_out, int out_size)
{
    const float* X     = (const float*)d_in[0];
    const float* W_in  = (const float*)d_in[1];
    const float* b_in  = (const float*)d_in[2];
    const float* Wf    = (const float*)d_in[3];
    const float* Uf    = (const float*)d_in[4];
    const float* bfp   = (const float*)d_in[5];
    const float* Wu    = (const float*)d_in[6];
    const float* Uu    = (const float*)d_in[7];
    const float* bup   = (const float*)d_in[8];
    const float* Wo1   = (const float*)d_in[9];
    const float* Uo1   = (const float*)d_in[10];
    const float* bo1   = (const float*)d_in[11];
    const float* Wo2   = (const float*)d_in[12];
    const float* bo2   = (const float*)d_in[13];
    const float* W_out = (const float*)d_in[14];
    const float* b_out = (const float*)d_in[15];

    // gate: As 55296B + Bs 41472B + sW 1536B + sBi 384B + Xs 2048B
    const int SMEM_GATE  = 3 * 9216 * 2 + 9 * 2304 * 2 + 384 * 4 + 96 * 4 + 128 * 16;
    // gemm2: As 55296B + Bs 27648B + sBi 256B
    const int SMEM_GEMM2 = 3 * 9216 * 2 + 3 * 4608 * 2 + 64 * 4;
    cudaFuncSetAttribute(k_gate_tc,  cudaFuncAttributeMaxDynamicSharedMemorySize, SMEM_GATE);
    cudaFuncSetAttribute(k_gemm2_tc, cudaFuncAttributeMaxDynamicSharedMemorySize, SMEM_GEMM2);

    k_transpose<<<dim3(16, 16, NLAYER * 4), 256>>>(Uf, Uu, Uo1, Wo2);
    k_init<<<BATCH, 256>>>(X, W_in, b_in);

    for (int l = 0; l < NLAYER; ++l) {
        const size_t w4 = (size_t)l * 4 * NND;     // [L,4,512] slice
        const size_t b1 = (size_t)l * NND;         // [L,1,512] slice
        k_gate_tc<<<dim3(16, BATCH / 128), 512, SMEM_GATE>>>(
            l, X,
            Wf + w4, bfp + b1,
            Wu + w4, bup + b1,
            Wo1 + w4, bo1 + b1);
        k_gemm2_tc<<<dim3(8, BATCH / 128), 512, SMEM_GEMM2>>>(l, bo2 + b1);
    }

    k_out<<<BATCH / 8, 256>>>(W_out, b_out, (float*)d_out);
}

// round 16
// speedup vs baseline: 4.7263x; 1.1971x over previous
#include <cuda_runtime.h>
#include <cuda_fp16.h>
#include <cstdint>

#define BATCH  131072
#define NND    512
#define NLAYER 3
#define NC     8           // 512 / 64 K-chunks
#define HST    72          // padded smem row stride (halves); 144B, LDSM conflict-free

// ---------------- scratch (device globals; no allocation allowed) ----------------
__device__ __half g_H0[(size_t)BATCH * NND];
__device__ __half g_H1[(size_t)BATCH * NND];
__device__ __half g_F [(size_t)BATCH * NND];
__device__ __half g_P [(size_t)BATCH * NND];
// transposed fp16 weights: [layer][gate: Uf,Uu,Uo1,Wo2][j][k]
__device__ __half g_UT[(size_t)NLAYER * 4 * NND * NND];

// ---------------- PTX helpers ----------------
__device__ __forceinline__ uint32_t smem_to_u32(const void* p) {
    uint32_t a;
    asm("{ .reg .u64 t; cvta.to.shared.u64 t, %1; cvt.u32.u64 %0, t; }" : "=r"(a) : "l"(p));
    return a;
}
__device__ __forceinline__ void cp_async16(uint32_t dst, const void* src) {
    asm volatile("cp.async.cg.shared.global [%0], [%1], 16;"
                 :: "r"(dst), "l"((unsigned long long)__cvta_generic_to_global((void*)src)) : "memory");
}
__device__ __forceinline__ void cp_commit() {
    asm volatile("cp.async.commit_group;" ::: "memory");
}
template <int N> __device__ __forceinline__ void cp_wait_group() {
    asm volatile("cp.async.wait_group %0;" :: "n"(N) : "memory");
}
// D += A(16x16,row) * B(16x8,col); fp16 inputs, fp32 accum
__device__ __forceinline__ void mmaf16(float* c, const uint32_t* a, uint32_t b0, uint32_t b1) {
    asm volatile(
        "mma.sync.aligned.m16n8k16.row.col.f32.f16.f16.f32 "
        "{%0,%1,%2,%3},{%4,%5,%6,%7},{%8,%9},{%0,%1,%2,%3};"
        : "+f"(c[0]), "+f"(c[1]), "+f"(c[2]), "+f"(c[3])
        : "r"(a[0]), "r"(a[1]), "r"(a[2]), "r"(a[3]), "r"(b0), "r"(b1));
}
__device__ __forceinline__ void ldsm4(uint32_t* r, uint32_t addr) {
    asm volatile("ldmatrix.sync.aligned.m8n8.x4.shared.b16 {%0,%1,%2,%3}, [%4];"
        : "=r"(r[0]), "=r"(r[1]), "=r"(r[2]), "=r"(r[3]) : "r"(addr));
}

// ---------------- activations ----------------
__device__ __forceinline__ float fsigmoid(float x) { return __fdividef(1.0f, 1.0f + __expf(-x)); }
__device__ __forceinline__ float ftanh_(float x)   { return 1.0f - __fdividef(2.0f, __expf(2.0f * x) + 1.0f); }
__device__ __forceinline__ float fsilu(float x)    { return x * fsigmoid(x); }

// ================= weight transpose (fp16): g_UT[l][g][j][k] = W[l][g][k][j] =================
__global__ __launch_bounds__(256) void k_transpose(
    const float* __restrict__ Uf, const float* __restrict__ Uu,
    const float* __restrict__ Uo1, const float* __restrict__ Wo2)
{
    __shared__ float t[32][33];
    int mat = blockIdx.z;
    int l = mat >> 2, g = mat & 3;
    const float* srcs[4] = {Uf, Uu, Uo1, Wo2};
    const float* src = srcs[g] + (size_t)l * NND * NND;
    __half* dst = g_UT + (size_t)mat * NND * NND;
    int x0 = blockIdx.x * 32, y0 = blockIdx.y * 32;
    int tx = threadIdx.x & 31, ty = threadIdx.x >> 5;
#pragma unroll
    for (int i = 0; i < 4; ++i)
        t[ty + 8 * i][tx] = src[(size_t)(y0 + ty + 8 * i) * NND + x0 + tx];
    __syncthreads();
#pragma unroll
    for (int i = 0; i < 4; ++i)
        dst[(size_t)(x0 + ty + 8 * i) * NND + y0 + tx] = __float2half_rn(t[tx][ty + 8 * i]);
}

// ================= kernel 1: H = fp16(silu(X @ W_in + b_in)), 2 cols/thread =================
__global__ __launch_bounds__(256) void k_init(
    const float* __restrict__ X, const float* __restrict__ W_in, const float* __restrict__ b_in)
{
    int idx = blockIdx.x * 256 + threadIdx.x;
    int m = idx >> 8;
    int j = (idx & 255) * 2;
    float4 xv = reinterpret_cast<const float4*>(X)[m];
    float a0 = b_in[j] + xv.x * W_in[j] + xv.y * W_in[NND + j]
             + xv.z * W_in[2 * NND + j] + xv.w * W_in[3 * NND + j];
    float a1 = b_in[j + 1] + xv.x * W_in[j + 1] + xv.y * W_in[NND + j + 1]
             + xv.z * W_in[2 * NND + j + 1] + xv.w * W_in[3 * NND + j + 1];
    *reinterpret_cast<__half2*>(&g_H0[(size_t)m * NND + j]) =
        __floats2half2_rn(fsilu(a0), fsilu(a1));
}

// ================= gate GEMM (fp16 mma.sync, 8 warps, 3-stage, 2 CTAs/SM) =================
// grid (16, 1024): x = 32-col j-block, y = 128-row m-block.
// 256 threads = 8 warps (4M x 2N); warp tile 32(M) x 16(N) per gate. BK=64.
__global__ __launch_bounds__(256, 2) void k_gate_tc(
    int layer, const float* __restrict__ X,
    const float* __restrict__ Wf_, const float* __restrict__ bf_,
    const float* __restrict__ Wu_, const float* __restrict__ bu_,
    const float* __restrict__ Wo_, const float* __restrict__ bo_)
{
    extern __shared__ __half smh[];
    __half* As = smh;                                    // 3 x 9216 halves (128 x HST)
    __half* Bs = smh + 3 * 9216;                         // 3 x 3 x 2304 halves (32 x HST per gate)
    float* sW  = (float*)(smh + 3 * 9216 + 9 * 2304);    // 384 floats: [gate][d][32]
    float* sBi = sW + 384;                               // 96
    float4* Xs = (float4*)(sBi + 96);                    // 128

    const int tid = threadIdx.x;
    const int lane = tid & 31;
    const int wid = tid >> 5;
    const int wM = wid & 3;                 // 4 M-warps x 32 rows
    const int wN = wid >> 2;                // 2 N-warps x 16 cols (per gate)
    const int gid = lane >> 2;
    const int tig = lane & 3;
    const int m0 = blockIdx.y * 128;
    const int j0 = blockIdx.x * 32;

    const __half* __restrict__ Hin = (layer & 1) ? g_H1 : g_H0;
    const __half* __restrict__ UT  = g_UT + (size_t)(layer * 4) * NND * NND;

    const uint32_t aBase = smem_to_u32(As);
    const uint32_t bBase = smem_to_u32(Bs);

    const int lr = lane & 7;
    uint32_t aoff[2];
#pragma unroll
    for (int mt = 0; mt < 2; ++mt)
        aoff[mt] = (uint32_t)((wM * 32 + mt * 16 + lr + ((lane >> 3) & 1) * 8) * HST * 2
                              + (lane >> 4) * 16);
    const uint32_t boff = (uint32_t)((wN * 16 + (lane >> 4) * 8 + lr) * HST * 2
                                     + ((lane >> 3) & 1) * 16);

    if (tid < 128) {
        // sW: 384 entries, 3 loads per thread
#pragma unroll
        for (int i = 0; i < 3; ++i) {
            int o = tid + 128 * i;
            int g = o >> 7, rem = o & 127, d = rem >> 5, jl = rem & 31;
            const float* Wsrc = (g == 0) ? Wf_ : ((g == 1) ? Wu_ : Wo_);
            sW[o] = Wsrc[d * NND + j0 + jl];
        }
        Xs[tid] = reinterpret_cast<const float4*>(X)[m0 + tid];
    }
    if (tid >= 128 && tid < 224) {
        int o = tid - 128;
        int g = o >> 5, jl = o & 31;
        sBi[o] = ((g == 0) ? bf_ : ((g == 1) ? bu_ : bo_))[j0 + jl];
    }

    float acc[3][2][2][4];                  // [gate][mt][nt][quad]
#pragma unroll
    for (int g = 0; g < 3; ++g)
#pragma unroll
        for (int mt = 0; mt < 2; ++mt)
#pragma unroll
            for (int nt = 0; nt < 2; ++nt)
#pragma unroll
                for (int q = 0; q < 4; ++q) acc[g][mt][nt][q] = 0.0f;

    auto loadA = [&](int s, int c) {
        const int k0 = c * 64;
#pragma unroll
        for (int i = 0; i < 4; ++i) {
            int e = tid + 256 * i, r = e >> 3, cc = e & 7;
            cp_async16(aBase + (s * 9216 + r * HST) * 2 + cc * 16,
                       Hin + (size_t)(m0 + r) * NND + k0 + cc * 8);
        }
    };
    auto loadB = [&](int s, int c) {
        const int k0 = c * 64;
#pragma unroll
        for (int i = 0; i < 3; ++i) {
            int e = tid + 256 * i;
            int g = e >> 8, rem = e & 255, r = rem >> 3, cc = rem & 7;
            cp_async16(bBase + ((s * 3 + g) * 2304 + r * HST) * 2 + cc * 16,
                       UT + (size_t)g * NND * NND + (size_t)(j0 + r) * NND + k0 + cc * 8);
        }
    };

    loadA(0, 0); loadB(0, 0); cp_commit();
    loadA(1, 1); loadB(1, 1); cp_commit();

#pragma unroll 1
    for (int c = 0; c < NC; ++c) {
        const int s = c % 3;
        if (c + 1 < NC) cp_wait_group<1>(); else cp_wait_group<0>();
        __syncthreads();
        if (c + 2 < NC) {
            const int s2 = (c + 2) % 3;
            loadA(s2, c + 2); loadB(s2, c + 2); cp_commit();
        }
        const uint32_t aS = aBase + (uint32_t)s * 18432;
#pragma unroll
        for (int ks = 0; ks < 4; ++ks) {
            uint32_t a[2][4];
            ldsm4(a[0], aS + aoff[0] + ks * 32);
            ldsm4(a[1], aS + aoff[1] + ks * 32);
#pragma unroll
            for (int g = 0; g < 3; ++g) {
                uint32_t b[4];
                ldsm4(b, bBase + (uint32_t)((s * 3 + g) * 4608) + boff + ks * 32);
                mmaf16(acc[g][0][0], a[0], b[0], b[1]);
                mmaf16(acc[g][1][0], a[1], b[0], b[1]);
                mmaf16(acc[g][0][1], a[0], b[2], b[3]);
                mmaf16(acc[g][1][1], a[1], b[2], b[3]);
            }
        }
    }

    // -------- epilogue: F = sigmoid(.), P = sigmoid(.)*tanh(.), fp16 stores --------
#pragma unroll
    for (int mt = 0; mt < 2; ++mt) {
#pragma unroll
        for (int rr = 0; rr < 2; ++rr) {
            int rloc = wM * 32 + mt * 16 + gid + rr * 8;
            int m = m0 + rloc;
            float4 xv = Xs[rloc];
#pragma unroll
            for (int nt = 0; nt < 2; ++nt) {
                int jl = wN * 16 + nt * 8 + 2 * tig;
                float fv[2], pv[2];
#pragma unroll
                for (int cc = 0; cc < 2; ++cc) {
                    int j = jl + cc;
                    float fpre = acc[0][mt][nt][rr * 2 + cc] + sBi[j]
                               + xv.x * sW[j]       + xv.y * sW[32 + j]
                               + xv.z * sW[64 + j]  + xv.w * sW[96 + j];
                    float upre = acc[1][mt][nt][rr * 2 + cc] + sBi[32 + j]
                               + xv.x * sW[128 + j] + xv.y * sW[160 + j]
                               + xv.z * sW[192 + j] + xv.w * sW[224 + j];
                    float opre = acc[2][mt][nt][rr * 2 + cc] + sBi[64 + j]
                               + xv.x * sW[256 + j] + xv.y * sW[288 + j]
                               + xv.z * sW[320 + j] + xv.w * sW[352 + j];
                    fv[cc] = fsigmoid(fpre);
                    pv[cc] = fsigmoid(upre) * ftanh_(opre);
                }
                size_t ga = (size_t)m * NND + j0 + jl;
                *reinterpret_cast<__half2*>(&g_F[ga]) = __floats2half2_rn(fv[0], fv[1]);
                *reinterpret_cast<__half2*>(&g_P[ga]) = __floats2half2_rn(pv[0], pv[1]);
            }
        }
    }
}

// ================= second GEMM: H_new = F*H + silu(P @ Wo2^T + bo2) =================
// grid (4, 1024): 256 threads = 8 warps (2M x 4N), warp tile 64x32, BK=64, 2 CTAs/SM.
__global__ __launch_bounds__(256, 2) void k_gemm2_tc(
    int layer, const float* __restrict__ b2)
{
    extern __shared__ __half smh[];
    __half* As = smh;                        // 3 x 9216 halves (128 x HST)
    __half* Bs = smh + 3 * 9216;             // 3 x 9216 halves (128 x HST)
    float* sBi = (float*)(smh + 6 * 9216);   // 128 floats

    const int tid = threadIdx.x;
    const int lane = tid & 31;
    const int wid = tid >> 5;
    const int wM = wid & 1;                  // 2 M-warps x 64 rows
    const int wN = wid >> 1;                 // 4 N-warps x 32 cols
    const int gid = lane >> 2;
    const int tig = lane & 3;
    const int m0 = blockIdx.y * 128;
    const int j0 = blockIdx.x * 128;

    const __half* __restrict__ Hin  = (layer & 1) ? g_H1 : g_H0;
    __half* __restrict__       Hout = (layer & 1) ? g_H0 : g_H1;
    const __half* __restrict__ WT = g_UT + (size_t)(layer * 4 + 3) * NND * NND;

    const uint32_t aBase = smem_to_u32(As);
    const uint32_t bBase = smem_to_u32(Bs);

    const int lr = lane & 7;
    uint32_t aoff[4];
#pragma unroll
    for (int mt = 0; mt < 4; ++mt)
        aoff[mt] = (uint32_t)((wM * 64 + mt * 16 + lr + ((lane >> 3) & 1) * 8) * HST * 2
                              + (lane >> 4) * 16);
    uint32_t boff[2];
#pragma unroll
    for (int p = 0; p < 2; ++p)
        boff[p] = (uint32_t)((wN * 32 + p * 16 + (lane >> 4) * 8 + lr) * HST * 2
                             + ((lane >> 3) & 1) * 16);

    if (tid < 128) sBi[tid] = b2[j0 + tid];

    float acc[4][4][4];                      // [mt][nt][quad]
#pragma unroll
    for (int mt = 0; mt < 4; ++mt)
#pragma unroll
        for (int nt = 0; nt < 4; ++nt)
#pragma unroll
            for (int q = 0; q < 4; ++q) acc[mt][nt][q] = 0.0f;

    auto loadA = [&](int s, int c) {
        const int k0 = c * 64;
#pragma unroll
        for (int i = 0; i < 4; ++i) {
            int e = tid + 256 * i, r = e >> 3, cc = e & 7;
            cp_async16(aBase + (s * 9216 + r * HST) * 2 + cc * 16,
                       g_P + (size_t)(m0 + r) * NND + k0 + cc * 8);
        }
    };
    auto loadB = [&](int s, int c) {
        const int k0 = c * 64;
#pragma unroll
        for (int i = 0; i < 4; ++i) {
            int e = tid + 256 * i, r = e >> 3, cc = e & 7;
            cp_async16(bBase + (s * 9216 + r * HST) * 2 + cc * 16,
                       WT + (size_t)(j0 + r) * NND + k0 + cc * 8);
        }
    };

    loadA(0, 0); loadB(0, 0); cp_commit();
    loadA(1, 1); loadB(1, 1); cp_commit();

#pragma unroll 1
    for (int c = 0; c < NC; ++c) {
        const int s = c % 3;
        if (c + 1 < NC) cp_wait_group<1>(); else cp_wait_group<0>();
        __syncthreads();
        if (c + 2 < NC) {
            const int s2 = (c + 2) % 3;
            loadA(s2, c + 2); loadB(s2, c + 2); cp_commit();
        }
        const uint32_t aS = aBase + (uint32_t)s * 18432;
        const uint32_t bS = bBase + (uint32_t)s * 18432;
#pragma unroll
        for (int ks = 0; ks < 4; ++ks) {
            uint32_t a[4][4], b[2][4];
            ldsm4(a[0], aS + aoff[0] + ks * 32);
            ldsm4(a[1], aS + aoff[1] + ks * 32);
            ldsm4(a[2], aS + aoff[2] + ks * 32);
            ldsm4(a[3], aS + aoff[3] + ks * 32);
            ldsm4(b[0], bS + boff[0] + ks * 32);
            ldsm4(b[1], bS + boff[1] + ks * 32);
#pragma unroll
            for (int mt = 0; mt < 4; ++mt) {
#pragma unroll
                for (int p = 0; p < 2; ++p) {
                    mmaf16(acc[mt][2 * p],     a[mt], b[p][0], b[p][1]);
                    mmaf16(acc[mt][2 * p + 1], a[mt], b[p][2], b[p][3]);
                }
            }
        }
    }

    // -------- epilogue: H_new = F*H + silu(acc + bias), fp16 stores --------
#pragma unroll
    for (int mt = 0; mt < 4; ++mt) {
#pragma unroll
        for (int rr = 0; rr < 2; ++rr) {
            int m = m0 + wM * 64 + mt * 16 + gid + rr * 8;
#pragma unroll
            for (int nt = 0; nt < 4; ++nt) {
                int jl = wN * 32 + nt * 8 + 2 * tig;
                size_t ga = (size_t)m * NND + j0 + jl;
                float2 Fv = __half22float2(*reinterpret_cast<const __half2*>(&g_F[ga]));
                float2 Hv = __half22float2(*reinterpret_cast<const __half2*>(&Hin[ga]));
                float h0 = Fv.x * Hv.x + fsilu(acc[mt][nt][rr * 2 + 0] + sBi[jl]);
                float h1 = Fv.y * Hv.y + fsilu(acc[mt][nt][rr * 2 + 1] + sBi[jl + 1]);
                *reinterpret_cast<__half2*>(&Hout[ga]) = __floats2half2_rn(h0, h1);
            }
        }
    }
}

// ================= kernel 4: out = silu(H @ W_out + b_out) =================
__global__ __launch_bounds__(256) void k_out(
    const float* __restrict__ W_out, const float* __restrict__ b_out, float* __restrict__ out)
{
    const __half* __restrict__ H = g_H1;   // after 3 layers: H0->H1->H0->H1
    const int warp = threadIdx.x >> 5;
    const int lane = threadIdx.x & 31;
    const int row = blockIdx.x * 8 + warp;
    const size_t base = (size_t)row * NND;
    float s = 0.0f;
#pragma unroll
    for (int t = 0; t < 8; ++t) {
        int o = lane * 2 + t * 64;
        float2 hv = __half22float2(*reinterpret_cast<const __half2*>(&H[base + o]));
        s += hv.x * W_out[o] + hv.y * W_out[o + 1];
    }
#pragma unroll
    for (int off = 16; off > 0; off >>= 1)
        s += __shfl_down_sync(0xffffffffu, s, off);
    if (lane == 0) out[row] = fsilu(s + b_out[0]);
}

// ================= launch =================
extern "C" void kernel_launch(void* const* d_in, const int* in_sizes, int n_in,
                              void* d_out, int out_size)
{
    const float* X     = (const float*)d_in[0];
    const float* W_in  = (const float*)d_in[1];
    const float* b_in  = (const float*)d_in[2];
    const float* Wf    = (const float*)d_in[3];
    const float* Uf    = (const float*)d_in[4];
    const float* bfp   = (const float*)d_in[5];
    const float* Wu    = (const float*)d_in[6];
    const float* Uu    = (const float*)d_in[7];
    const float* bup   = (const float*)d_in[8];
    const float* Wo1   = (const float*)d_in[9];
    const float* Uo1   = (const float*)d_in[10];
    const float* bo1   = (const float*)d_in[11];
    const float* Wo2   = (const float*)d_in[12];
    const float* bo2   = (const float*)d_in[13];
    const float* W_out = (const float*)d_in[14];
    const float* b_out = (const float*)d_in[15];

    // gate: As 55296B + Bs 41472B + sW 1536B + sBi 384B + Xs 2048B = 100736B
    const int SMEM_GATE  = 3 * 9216 * 2 + 9 * 2304 * 2 + 384 * 4 + 96 * 4 + 128 * 16;
    // gemm2: As 55296B + Bs 55296B + sBi 512B = 111104B
    const int SMEM_GEMM2 = 6 * 9216 * 2 + 128 * 4;
    cudaFuncSetAttribute(k_gate_tc,  cudaFuncAttributeMaxDynamicSharedMemorySize, SMEM_GATE);
    cudaFuncSetAttribute(k_gemm2_tc, cudaFuncAttributeMaxDynamicSharedMemorySize, SMEM_GEMM2);

    k_transpose<<<dim3(16, 16, NLAYER * 4), 256>>>(Uf, Uu, Uo1, Wo2);
    k_init<<<BATCH, 256>>>(X, W_in, b_in);

    for (int l = 0; l < NLAYER; ++l) {
        const size_t w4 = (size_t)l * 4 * NND;     // [L,4,512] slice
        const size_t b1 = (size_t)l * NND;         // [L,1,512] slice
        k_gate_tc<<<dim3(16, BATCH / 128), 256, SMEM_GATE>>>(
            l, X,
            Wf + w4, bfp + b1,
            Wu + w4, bup + b1,
            Wo1 + w4, bo1 + b1);
        k_gemm2_tc<<<dim3(4, BATCH / 128), 256, SMEM_GEMM2>>>(l, bo2 + b1);
    }

    k_out<<<BATCH / 8, 256>>>(W_out, b_out, (float*)d_out);
}